// round 11
// baseline (speedup 1.0000x reference)
#include <cuda_runtime.h>

// ---------------- problem constants ----------------
#define S_LEN  512
#define DIN    5
#define HID    128
#define GATES  512
#define BATCH  1024
#define NBLK   147     // recurrence blocks: 146 x 7 rows + 1 x 2 rows
#define RPB    7       // rows per block (logical)
#define BST    8       // row stride in g_h1 / g_xg1 (padded)
#define NG     32      // k-groups (of 4) per 128-wide K
#define NSM    23      // k-groups cached in smem (rest in registers)
#define NTH    384     // phase threads = 128 j x 3 kh

// phase smem layout (float offsets)
#define OFF_WC  0
#define OFF_HA  (NSM*GATES*4)            // 47104 : hA [4][128]
#define OFF_HB  (OFF_HA + 512)           // 47616 : hB [3][128] (512 reserved)
#define OFF_XP  (OFF_HB + 512)           // 48128 : [2 half][2 slot][4 r][128 j][4 q]
#define PH_SMEM_BYTES ((OFF_XP + 8192)*4)   // 225280

// gemm smem: Ws [32 g][128 c][4k] = 16384 floats + Ht 2 x 4096 (4 t x 8 b x 128 j)
#define GM_THREADS 512
#define GM_HT_OFF  (NG*128*4)            // 16384 floats
#define GM_SMEM_BYTES ((GM_HT_OFF + 2*4096)*4)   // 98304 -> 2 CTAs/SM

// ---------------- global scratch (static) ----------------
__device__ __align__(16) float g_P1[NG * GATES * 4];   // packed w_hh0
__device__ __align__(16) float g_P2[NG * GATES * 4];   // packed w_hh1
__device__ __align__(16) float g_P3[NG * GATES * 4];   // packed w_ih1
__device__ __align__(16) float g_h1 [(size_t)NBLK * S_LEN * BST * HID];    // [blk][t][b8][j]
__device__ __align__(16) float g_xg1[(size_t)NBLK * S_LEN * GATES * BST];  // [blk][t][col][b8]

// ---------------- helpers ----------------
typedef unsigned long long u64;
__device__ __forceinline__ void ffma2(u64 &d, u64 a, u64 b) {
    asm("fma.rn.f32x2 %0, %1, %2, %0;" : "+l"(d) : "l"(a), "l"(b));
}
__device__ __forceinline__ float flo(u64 v) { return __uint_as_float((unsigned)v); }
__device__ __forceinline__ float fhi(u64 v) { return __uint_as_float((unsigned)(v >> 32)); }
__device__ __forceinline__ float sigf(float x) {
    return __fdividef(1.0f, 1.0f + __expf(-x));
}
__device__ __forceinline__ float tanhf_fast(float x) {
    float e = __expf(2.0f * x);
    return 1.0f - __fdividef(2.0f, e + 1.0f);
}

// smem-group accumulation over NB batch rows
template<int G0, int G1, int NB>
__device__ __forceinline__ void accum_smem(u64 (&acc)[4][NB],
                                           const ulonglong2* __restrict__ W,
                                           const ulonglong2* __restrict__ H,
                                           int j) {
#pragma unroll
    for (int g = G0; g < G1; g++) {
        ulonglong2 w[4];
#pragma unroll
        for (int q = 0; q < 4; q++) w[q] = W[g * GATES + q * HID + j];
#pragma unroll
        for (int b = 0; b < NB; b++) {
            ulonglong2 hv = H[b * 32 + g];
#pragma unroll
            for (int q = 0; q < 4; q++) {
                ffma2(acc[q][b], w[q].x, hv.x);
                ffma2(acc[q][b], w[q].y, hv.y);
            }
        }
    }
}

template<int NB>
__device__ __forceinline__ void gemm_body(int kh, const ulonglong2* __restrict__ WcD,
                                          const ulonglong2 (&wr)[3][4], int gb,
                                          const ulonglong2* __restrict__ H, int j,
                                          float (&pr)[4][NB]) {
    u64 acc[4][NB];
#pragma unroll
    for (int q = 0; q < 4; q++)
#pragma unroll
        for (int b = 0; b < NB; b++) acc[q][b] = 0ull;
    if (kh == 0)      accum_smem<0,  7,  NB>(acc, WcD, H, j);
    else if (kh == 1) accum_smem<7,  14, NB>(acc, WcD, H, j);
    else              accum_smem<14, NSM, NB>(acc, WcD, H, j);
#pragma unroll
    for (int s = 0; s < 3; s++) {
#pragma unroll
        for (int b = 0; b < NB; b++) {
            ulonglong2 hv = H[b * 32 + gb + s];
#pragma unroll
            for (int q = 0; q < 4; q++) {
                ffma2(acc[q][b], wr[s][q].x, hv.x);
                ffma2(acc[q][b], wr[s][q].y, hv.y);
            }
        }
    }
#pragma unroll
    for (int q = 0; q < 4; q++)
#pragma unroll
        for (int b = 0; b < NB; b++) pr[q][b] = flo(acc[q][b]) + fhi(acc[q][b]);
}

// ---------------- K1: pack weights ----------------
__global__ void pack_kernel(const float* __restrict__ whh0,
                            const float* __restrict__ whh1,
                            const float* __restrict__ wih1) {
    int i = blockIdx.x * blockDim.x + threadIdx.x;
    if (i >= GATES * HID) return;
    int col = i / HID, k = i % HID;
    int g = k >> 2, dk = k & 3;
    size_t o = ((size_t)g * GATES + col) * 4 + dk;
    g_P1[o] = whh0[col * HID + k];
    g_P2[o] = whh1[col * HID + k];
    g_P3[o] = wih1[col * HID + k];
}

// ---------------- K3: xg1 = h1 @ w_ih1^T + biases ----------------
// grid (4 ch, NBLK), 512 thr, 2 CTAs/SM. CTA: 128 cols x 512 t (tiles of 4 t).
// thread: cl = tid&127 -> 1 col; rw = tid>>7 -> t within 4-t tile; all 8 b rows.
__global__ void __launch_bounds__(GM_THREADS, 2) xg1_gemm(const float* __restrict__ bih1,
                                                          const float* __restrict__ bhh1) {
    extern __shared__ float sm[];
    float4* Ws4 = (float4*)sm;
    float*  Ht  = sm + GM_HT_OFF;

    const int tid = threadIdx.x;
    const int ch  = blockIdx.x, blk = blockIdx.y;
    const int cl  = tid & 127;
    const int rw  = tid >> 7;                 // 0..3 : t within tile
    const int col = ch * 128 + cl;

    // weight slice: 32 g x 128 cols (float4 over 4 k's)
    {
        const float4* P34 = (const float4*)g_P3;
        for (int i = tid; i < NG * 128; i += GM_THREADS) {
            int g = i >> 7, c = i & 127;
            Ws4[i] = __ldg(&P34[g * GATES + ch * 128 + c]);
        }
    }
    const float bias = __ldg(bih1 + col) + __ldg(bhh1 + col);

    // preload tile 0 (4 t x 8 b x 128 j = 1024 float4; 2 per thread)
    {
        const float4* hsrc = (const float4*)(g_h1 + (size_t)(blk * S_LEN) * (BST * HID));
        ((float4*)Ht)[tid * 2]     = __ldg(hsrc + tid * 2);
        ((float4*)Ht)[tid * 2 + 1] = __ldg(hsrc + tid * 2 + 1);
    }
    __syncthreads();

    const ulonglong2* WsD = (const ulonglong2*)sm;
    int pb = 0;
    for (int tt = 0; tt < S_LEN / 4; tt++) {          // 128 tiles of 4 t
        const int t = tt * 4 + rw;
        const bool has = (tt + 1 < S_LEN / 4);
        float4 pre0, pre1;
        if (has) {
            const float4* hsrc = (const float4*)(g_h1 +
                (size_t)(blk * S_LEN + (tt + 1) * 4) * (BST * HID));
            pre0 = __ldg(hsrc + tid * 2);
            pre1 = __ldg(hsrc + tid * 2 + 1);
        }

        const ulonglong2* HtD = (const ulonglong2*)(Ht + pb * 4096);
        u64 acc[BST] = {0,0,0,0,0,0,0,0};
#pragma unroll 8
        for (int g = 0; g < NG; g++) {
            ulonglong2 w = WsD[g * 128 + cl];
#pragma unroll
            for (int b = 0; b < BST; b++) {
                ulonglong2 hv = HtD[(rw * BST + b) * 32 + g];
                ffma2(acc[b], w.x, hv.x);
                ffma2(acc[b], w.y, hv.y);
            }
        }
        float o[BST];
#pragma unroll
        for (int b = 0; b < BST; b++) o[b] = flo(acc[b]) + fhi(acc[b]) + bias;
        float4* dst = (float4*)(g_xg1 + ((size_t)(blk * S_LEN + t) * GATES + col) * BST);
        dst[0] = make_float4(o[0], o[1], o[2], o[3]);
        dst[1] = make_float4(o[4], o[5], o[6], o[7]);

        if (has) {
            ((float4*)(Ht + (pb ^ 1) * 4096))[tid * 2]     = pre0;
            ((float4*)(Ht + (pb ^ 1) * 4096))[tid * 2 + 1] = pre1;
        }
        __syncthreads();
        pb ^= 1;
    }
}

// ---------------- K2/K4: recurrent phases, batch-half pipelined, 7 rows/block ----
// Half A = local rows 0-3 (4), half B = local rows 4-6 (3).
// alpha: GEMM_A(t) + finalize_B(t-1). beta: GEMM_B(t) + finalize_A(t).
template<int PHASE>
__global__ void __launch_bounds__(NTH, 1) lstm_phase(
    const float* __restrict__ x,
    const float* __restrict__ wih0,
    const float* __restrict__ bih,
    const float* __restrict__ bhh,
    const float* __restrict__ fcw,
    const float* __restrict__ fcb,
    float* __restrict__ out)
{
    extern __shared__ float sm[];
    const float* Pg = (PHASE == 1) ? g_P1 : g_P2;

    const int tid = threadIdx.x;
    const int j   = tid & (HID - 1);
    const int kh  = tid >> 7;
    const int blk = blockIdx.x;
    const int bg0 = blk * RPB;
    const int valid = (BATCH - bg0 < RPB) ? (BATCH - bg0) : RPB;
    const int gb  = NSM + kh * 3;

    ulonglong2 wr[3][4];
    {
        const ulonglong2* PgD = (const ulonglong2*)Pg;
#pragma unroll
        for (int s = 0; s < 3; s++)
#pragma unroll
            for (int q = 0; q < 4; q++)
                wr[s][q] = __ldg(&PgD[(gb + s) * GATES + q * HID + j]);
    }

    float bias[4], wihr[4][DIN];
    if (PHASE == 1 && kh < 2) {
#pragma unroll
        for (int q = 0; q < 4; q++) {
            int r = q * HID + j;
            bias[q] = __ldg(bih + r) + __ldg(bhh + r);
#pragma unroll
            for (int d = 0; d < DIN; d++) wihr[q][d] = __ldg(wih0 + r * DIN + d);
        }
    }

    {
        const float4* src = (const float4*)Pg;
        float4*       dst = (float4*)(sm + OFF_WC);
        for (int i = tid; i < NSM * GATES; i += NTH) dst[i] = __ldg(src + i);
    }
    for (int i = tid; i < 1024; i += NTH) sm[OFF_HA + i] = 0.f;
    __syncthreads();

    const ulonglong2* WcD = (const ulonglong2*)(sm + OFF_WC);

    float c[2][2] = {{0.f, 0.f}, {0.f, 0.f}};
    float2 xqA[4], xqB[4];
    float  xvA[2][DIN], xvB[2][DIN];

    // -------- export helpers --------
    auto exportA = [&](float (&pr)[4][4], float (&prOwn)[4][2]) {
        float* XP = sm + OFF_XP;               // half A
        if (kh == 0) {
#pragma unroll
            for (int r = 2; r < 4; r++)
                *(float4*)(XP + r * 512 + j * 4) =
                    make_float4(pr[0][r], pr[1][r], pr[2][r], pr[3][r]);
#pragma unroll
            for (int q = 0; q < 4; q++) { prOwn[q][0] = pr[q][0]; prOwn[q][1] = pr[q][1]; }
        } else if (kh == 1) {
#pragma unroll
            for (int r = 0; r < 2; r++)
                *(float4*)(XP + r * 512 + j * 4) =
                    make_float4(pr[0][r], pr[1][r], pr[2][r], pr[3][r]);
#pragma unroll
            for (int q = 0; q < 4; q++) { prOwn[q][0] = pr[q][2]; prOwn[q][1] = pr[q][3]; }
        } else {
#pragma unroll
            for (int r = 0; r < 4; r++)
                *(float4*)(XP + 2048 + r * 512 + j * 4) =
                    make_float4(pr[0][r], pr[1][r], pr[2][r], pr[3][r]);
        }
    };
    auto exportB = [&](float (&pr)[4][3], float (&prOwn)[4][3]) {
        float* XP = sm + OFF_XP + 4096;        // half B
        if (kh == 0) {
            *(float4*)(XP + 2 * 512 + j * 4) =
                make_float4(pr[0][2], pr[1][2], pr[2][2], pr[3][2]);
#pragma unroll
            for (int q = 0; q < 4; q++) { prOwn[q][0] = pr[q][0]; prOwn[q][1] = pr[q][1]; }
        } else if (kh == 1) {
#pragma unroll
            for (int r = 0; r < 2; r++)
                *(float4*)(XP + r * 512 + j * 4) =
                    make_float4(pr[0][r], pr[1][r], pr[2][r], pr[3][r]);
#pragma unroll
            for (int q = 0; q < 4; q++) prOwn[q][0] = pr[q][2];
        } else {
#pragma unroll
            for (int r = 0; r < 3; r++)
                *(float4*)(XP + 2048 + r * 512 + j * 4) =
                    make_float4(pr[0][r], pr[1][r], pr[2][r], pr[3][r]);
        }
    };

    auto finalize_half = [&](int hoff, int half, int t, const float* prOwn0, const float* prOwn1,
                             float2 (&xq)[4], float (&xv)[2][DIN]) {
        const float* XP = sm + OFF_XP + half * 4096;
        const int nown = (kh == 0) ? 2 : (half == 0 ? 2 : 1);
#pragma unroll
        for (int r2 = 0; r2 < 2; r2++) {
            if (r2 >= nown) break;
            int rloc = 2 * kh + r2;
            const float* po = (r2 == 0) ? prOwn0 : prOwn1;
            float4 p0 = *(const float4*)(XP + rloc * 512 + j * 4);
            float4 p1 = *(const float4*)(XP + 2048 + rloc * 512 + j * 4);
            float gate[4];
            gate[0] = po[0] + p0.x + p1.x;
            gate[1] = po[1] + p0.y + p1.y;
            gate[2] = po[2] + p0.z + p1.z;
            gate[3] = po[3] + p0.w + p1.w;
            if (PHASE == 1) {
#pragma unroll
                for (int q = 0; q < 4; q++) {
                    float s = bias[q];
#pragma unroll
                    for (int d = 0; d < DIN; d++) s = fmaf(wihr[q][d], xv[r2][d], s);
                    gate[q] += s;
                }
            } else {
                gate[0] += (r2 == 0 ? xq[0].x : xq[0].y);
                gate[1] += (r2 == 0 ? xq[1].x : xq[1].y);
                gate[2] += (r2 == 0 ? xq[2].x : xq[2].y);
                gate[3] += (r2 == 0 ? xq[3].x : xq[3].y);
            }
            float cc = sigf(gate[1]) * c[half][r2] + sigf(gate[0]) * tanhf_fast(gate[2]);
            c[half][r2] = cc;
            float h = sigf(gate[3]) * tanhf_fast(cc);
            sm[hoff + rloc * HID + j] = h;
            if (PHASE == 1)
                g_h1[((size_t)(blk * S_LEN + t) * BST + half * 4 + rloc) * HID + j] = h;
        }
    };

    auto load_inputs = [&](int half, int t, float2 (&xq)[4], float (&xv)[2][DIN]) {
        if (kh >= 2) return;
        if (PHASE == 2) {
            const float* xp = g_xg1 + (size_t)(blk * S_LEN + t) * (GATES * BST);
            int off = half * 4 + 2 * kh;
#pragma unroll
            for (int q = 0; q < 4; q++)
                xq[q] = __ldg((const float2*)(xp + (q * HID + j) * BST + off));
        } else {
#pragma unroll
            for (int r2 = 0; r2 < 2; r2++) {
                int gr = bg0 + half * 4 + 2 * kh + r2;
                if (gr > BATCH - 1) gr = BATCH - 1;
                const float* xr = x + ((size_t)gr * S_LEN + t) * DIN;
#pragma unroll
                for (int d = 0; d < DIN; d++) xv[r2][d] = __ldg(xr + d);
            }
        }
    };

    float prOwnA[4][2];
    float prOwnBv[4][3];

    for (int t = 0; t < S_LEN; t++) {
        // ---- alpha: GEMM_A(t) + finalize_B(t-1) ----
        load_inputs(0, t, xqA, xvA);
        if (t > 0 && kh < 2) {
            float o0[4] = {prOwnBv[0][0], prOwnBv[1][0], prOwnBv[2][0], prOwnBv[3][0]};
            float o1[4] = {prOwnBv[0][1], prOwnBv[1][1], prOwnBv[2][1], prOwnBv[3][1]};
            finalize_half(OFF_HB, 1, t - 1, o0, o1, xqB, xvB);
        }
        {
            float prA[4][4];
            gemm_body<4>(kh, WcD, wr, gb, (const ulonglong2*)(sm + OFF_HA), j, prA);
            exportA(prA, prOwnA);
            __syncthreads();
            // ---- beta: GEMM_B(t) + finalize_A(t) ----
            load_inputs(1, t, xqB, xvB);
            if (kh < 2) {
                float o0[4] = {prOwnA[0][0], prOwnA[1][0], prOwnA[2][0], prOwnA[3][0]};
                float o1[4] = {prOwnA[0][1], prOwnA[1][1], prOwnA[2][1], prOwnA[3][1]};
                finalize_half(OFF_HA, 0, t, o0, o1, xqA, xvA);
            }
        }
        {
            float prBt[4][3];
            gemm_body<3>(kh, WcD, wr, gb, (const ulonglong2*)(sm + OFF_HB), j, prBt);
            exportB(prBt, prOwnBv);
        }
        __syncthreads();
    }
    // drain: finalize_B(511)
    if (kh < 2) {
        float o0[4] = {prOwnBv[0][0], prOwnBv[1][0], prOwnBv[2][0], prOwnBv[3][0]};
        float o1[4] = {prOwnBv[0][1], prOwnBv[1][1], prOwnBv[2][1], prOwnBv[3][1]};
        finalize_half(OFF_HB, 1, S_LEN - 1, o0, o1, xqB, xvB);
    }
    __syncthreads();

    if (PHASE == 2 && tid < 224) {
        int w = tid >> 5, lane = tid & 31;
        if (w < valid) {
            const float* hrow = sm + (w < 4 ? OFF_HA + w * HID : OFF_HB + (w - 4) * HID);
            float s = 0.f;
#pragma unroll
            for (int m = 0; m < HID; m += 32)
                s += hrow[lane + m] * __ldg(fcw + lane + m);
#pragma unroll
            for (int o = 16; o > 0; o >>= 1) s += __shfl_down_sync(0xffffffffu, s, o);
            if (lane == 0) out[bg0 + w] = s + __ldg(fcb);
        }
    }
}

// ---------------- launch ----------------
extern "C" void kernel_launch(void* const* d_in, const int* in_sizes, int n_in,
                              void* d_out, int out_size) {
    const float* x    = (const float*)d_in[0];
    const float* wih0 = (const float*)d_in[1];
    const float* whh0 = (const float*)d_in[2];
    const float* bih0 = (const float*)d_in[3];
    const float* bhh0 = (const float*)d_in[4];
    const float* wih1 = (const float*)d_in[5];
    const float* whh1 = (const float*)d_in[6];
    const float* bih1 = (const float*)d_in[7];
    const float* bhh1 = (const float*)d_in[8];
    const float* fcw  = (const float*)d_in[9];
    const float* fcb  = (const float*)d_in[10];
    float* out = (float*)d_out;
    (void)in_sizes; (void)n_in; (void)out_size;

    cudaFuncSetAttribute(lstm_phase<1>, cudaFuncAttributeMaxDynamicSharedMemorySize, PH_SMEM_BYTES);
    cudaFuncSetAttribute(lstm_phase<2>, cudaFuncAttributeMaxDynamicSharedMemorySize, PH_SMEM_BYTES);
    cudaFuncSetAttribute(xg1_gemm,      cudaFuncAttributeMaxDynamicSharedMemorySize, GM_SMEM_BYTES);

    pack_kernel<<<(GATES * HID + 255) / 256, 256>>>(whh0, whh1, wih1);
    lstm_phase<1><<<NBLK, NTH, PH_SMEM_BYTES>>>(x, wih0, bih0, bhh0, fcw, fcb, out);
    xg1_gemm<<<dim3(4, NBLK), GM_THREADS, GM_SMEM_BYTES>>>(bih1, bhh1);
    lstm_phase<2><<<NBLK, NTH, PH_SMEM_BYTES>>>(x, wih0, bih1, bhh1, fcw, fcb, out);
}

// round 12
// speedup vs baseline: 1.1856x; 1.1856x over previous
#include <cuda_runtime.h>

// ---------------- problem constants ----------------
#define S_LEN  512
#define DIN    5
#define HID    128
#define GATES  512
#define BATCH  1024
#define NBLK   147     // recurrence blocks: 146 x 7 rows + 1 x 2 rows
#define RPB    7       // rows per block (logical)
#define BST    8       // row stride in g_h1 / g_xg1 (padded)
#define NG     32      // k-groups (of 4) per 128-wide K
#define NSM    23      // k-groups cached in smem (rest in registers)
#define NTH    384     // phase threads = 128 j x 3 kh

// phase smem layout (float offsets)
#define OFF_WC  0
#define OFF_HA  (NSM*GATES*4)            // 47104 : hA [4][128]
#define OFF_HB  (OFF_HA + 512)           // 47616 : hB [3][128] (512 reserved)
#define OFF_XP  (OFF_HB + 512)           // 48128 : [2 half][2 slot][4 r][128 j][4 q]
#define PH_SMEM_BYTES ((OFF_XP + 8192)*4)   // 225280

// gemm smem: Ws [32 g][256 c][4k] = 32768 floats + Ht 2 x 8192 (4t x 2blk x 8r x 128j)
#define GM_THREADS 512
#define GM_WS_FLOATS (NG*256*4)          // 32768
#define GM_HT_OFF  GM_WS_FLOATS
#define GM_TILE_FLOATS (4*2*BST*HID)     // 8192
#define GM_SMEM_BYTES ((GM_WS_FLOATS + 2*GM_TILE_FLOATS)*4)   // 196608

// ---------------- global scratch (static) ----------------
__device__ __align__(16) float g_P1[NG * GATES * 4];   // packed w_hh0
__device__ __align__(16) float g_P2[NG * GATES * 4];   // packed w_hh1
__device__ __align__(16) float g_P3[NG * GATES * 4];   // packed w_ih1
__device__ __align__(16) float g_h1 [(size_t)NBLK * S_LEN * BST * HID];    // [blk][t][b8][j]
__device__ __align__(16) float g_xg1[(size_t)NBLK * S_LEN * GATES * BST];  // [blk][t][col][b8]

// ---------------- helpers ----------------
typedef unsigned long long u64;
__device__ __forceinline__ void ffma2(u64 &d, u64 a, u64 b) {
    asm("fma.rn.f32x2 %0, %1, %2, %0;" : "+l"(d) : "l"(a), "l"(b));
}
__device__ __forceinline__ float flo(u64 v) { return __uint_as_float((unsigned)v); }
__device__ __forceinline__ float fhi(u64 v) { return __uint_as_float((unsigned)(v >> 32)); }
__device__ __forceinline__ float sigf(float x) {
    return __fdividef(1.0f, 1.0f + __expf(-x));
}
__device__ __forceinline__ float tanhf_fast(float x) {
    float e = __expf(2.0f * x);
    return 1.0f - __fdividef(2.0f, e + 1.0f);
}

// smem-group accumulation over NB batch rows
template<int G0, int G1, int NB>
__device__ __forceinline__ void accum_smem(u64 (&acc)[4][NB],
                                           const ulonglong2* __restrict__ W,
                                           const ulonglong2* __restrict__ H,
                                           int j) {
#pragma unroll
    for (int g = G0; g < G1; g++) {
        ulonglong2 w[4];
#pragma unroll
        for (int q = 0; q < 4; q++) w[q] = W[g * GATES + q * HID + j];
#pragma unroll
        for (int b = 0; b < NB; b++) {
            ulonglong2 hv = H[b * 32 + g];
#pragma unroll
            for (int q = 0; q < 4; q++) {
                ffma2(acc[q][b], w[q].x, hv.x);
                ffma2(acc[q][b], w[q].y, hv.y);
            }
        }
    }
}

template<int NB>
__device__ __forceinline__ void gemm_body(int kh, const ulonglong2* __restrict__ WcD,
                                          const ulonglong2 (&wr)[3][4], int gb,
                                          const ulonglong2* __restrict__ H, int j,
                                          float (&pr)[4][NB]) {
    u64 acc[4][NB];
#pragma unroll
    for (int q = 0; q < 4; q++)
#pragma unroll
        for (int b = 0; b < NB; b++) acc[q][b] = 0ull;
    if (kh == 0)      accum_smem<0,  7,  NB>(acc, WcD, H, j);
    else if (kh == 1) accum_smem<7,  14, NB>(acc, WcD, H, j);
    else              accum_smem<14, NSM, NB>(acc, WcD, H, j);
#pragma unroll
    for (int s = 0; s < 3; s++) {
#pragma unroll
        for (int b = 0; b < NB; b++) {
            ulonglong2 hv = H[b * 32 + gb + s];
#pragma unroll
            for (int q = 0; q < 4; q++) {
                ffma2(acc[q][b], wr[s][q].x, hv.x);
                ffma2(acc[q][b], wr[s][q].y, hv.y);
            }
        }
    }
#pragma unroll
    for (int q = 0; q < 4; q++)
#pragma unroll
        for (int b = 0; b < NB; b++) pr[q][b] = flo(acc[q][b]) + fhi(acc[q][b]);
}

// ---------------- K1: pack weights ----------------
__global__ void pack_kernel(const float* __restrict__ whh0,
                            const float* __restrict__ whh1,
                            const float* __restrict__ wih1) {
    int i = blockIdx.x * blockDim.x + threadIdx.x;
    if (i >= GATES * HID) return;
    int col = i / HID, k = i % HID;
    int g = k >> 2, dk = k & 3;
    size_t o = ((size_t)g * GATES + col) * 4 + dk;
    g_P1[o] = whh0[col * HID + k];
    g_P2[o] = whh1[col * HID + k];
    g_P3[o] = wih1[col * HID + k];
}

// ---------------- K3: xg1 = h1 @ w_ih1^T + biases ----------------
// grid (2 ch, 74 bp, 4 tq) = 592 CTAs (exactly 4 waves), 512 thr, 1 CTA/SM.
// CTA: 256 cols x 2 batch-blocks x 128 t (tiles of 4 t).
// thread: cp = tid&127 -> 2 cols; rw = tid>>7 -> 1 t of the 4-t tile; 14 rows (2 blk x 7).
// Tile layout Ht: [t(4)][bs(2)][r(8)][j(128)] floats.
__global__ void __launch_bounds__(GM_THREADS, 1) xg1_gemm(const float* __restrict__ bih1,
                                                          const float* __restrict__ bhh1) {
    extern __shared__ float sm[];
    float4* Ws4 = (float4*)sm;
    float*  Ht  = sm + GM_HT_OFF;

    const int tid = threadIdx.x;
    const int ch  = blockIdx.x, bp = blockIdx.y, tq = blockIdx.z;
    const int cp  = tid & 127;
    const int rw  = tid >> 7;                 // 0..3 : t within tile
    const int c0  = ch * 256 + cp * 2;
    const int t0  = tq * (S_LEN / 4);         // 128 t per CTA
    const int blk0 = bp * 2;
    const int blk1 = (bp * 2 + 1 < NBLK) ? (bp * 2 + 1) : (NBLK - 1);

    // weight half: 32 g x 256 cols
    {
        const float4* P34 = (const float4*)g_P3;
        for (int i = tid; i < NG * 256; i += GM_THREADS) {
            int g = i >> 8, c = i & 255;
            Ws4[i] = __ldg(&P34[g * GATES + ch * 256 + c]);
        }
    }
    const float bs0 = __ldg(bih1 + c0)     + __ldg(bhh1 + c0);
    const float bs1 = __ldg(bih1 + c0 + 1) + __ldg(bhh1 + c0 + 1);

    // tile loader: i enumerates (t, bs, rj): idx = t*512 + bs*256 + rj (float4 units)
    auto tile_src = [&](int i, int tbase) -> float4 {
        int t_  = i >> 9;
        int bsp = (i >> 8) & 1;
        int rj  = i & 255;
        int blkid = bsp ? blk1 : blk0;
        const float4* src = (const float4*)g_h1 + (size_t)(blkid * S_LEN + tbase + t_) * 256;
        return __ldg(src + rj);
    };

    // preload tile 0
    {
        float4* dst = (float4*)Ht;
#pragma unroll
        for (int k = 0; k < 4; k++) dst[tid + 512 * k] = tile_src(tid + 512 * k, t0);
    }
    __syncthreads();

    const ulonglong2* WsD = (const ulonglong2*)sm;
    int pb = 0;
    for (int tt = 0; tt < 32; tt++) {
        const int t = t0 + tt * 4 + rw;
        const bool has = (tt + 1 < 32);
        float4 pre[4];
        if (has) {
#pragma unroll
            for (int k = 0; k < 4; k++) pre[k] = tile_src(tid + 512 * k, t0 + (tt + 1) * 4);
        }

        const ulonglong2* HtD = (const ulonglong2*)(Ht + pb * GM_TILE_FLOATS);
        u64 a0[14], a1[14];
#pragma unroll
        for (int m = 0; m < 14; m++) { a0[m] = 0ull; a1[m] = 0ull; }

#pragma unroll 4
        for (int g = 0; g < NG; g++) {
            ulonglong2 w0 = WsD[g * 256 + cp * 2];
            ulonglong2 w1 = WsD[g * 256 + cp * 2 + 1];
#pragma unroll
            for (int bs = 0; bs < 2; bs++) {
#pragma unroll
                for (int r = 0; r < RPB; r++) {
                    ulonglong2 hv = HtD[((rw * 2 + bs) * BST + r) * 32 + g];
                    int m = bs * RPB + r;
                    ffma2(a0[m], w0.x, hv.x); ffma2(a0[m], w0.y, hv.y);
                    ffma2(a1[m], w1.x, hv.x); ffma2(a1[m], w1.y, hv.y);
                }
            }
        }

#pragma unroll
        for (int bs = 0; bs < 2; bs++) {
            int blkid = bs ? blk1 : blk0;
            float o0[BST], o1[BST];
#pragma unroll
            for (int r = 0; r < RPB; r++) {
                int m = bs * RPB + r;
                o0[r] = flo(a0[m]) + fhi(a0[m]) + bs0;
                o1[r] = flo(a1[m]) + fhi(a1[m]) + bs1;
            }
            o0[7] = 0.f; o1[7] = 0.f;
            float* dst = g_xg1 + ((size_t)(blkid * S_LEN + t) * GATES + c0) * BST;
            ((float4*)dst)[0] = make_float4(o0[0], o0[1], o0[2], o0[3]);
            ((float4*)dst)[1] = make_float4(o0[4], o0[5], o0[6], o0[7]);
            ((float4*)dst)[2] = make_float4(o1[0], o1[1], o1[2], o1[3]);
            ((float4*)dst)[3] = make_float4(o1[4], o1[5], o1[6], o1[7]);
        }

        if (has) {
            float4* dst = (float4*)(Ht + (pb ^ 1) * GM_TILE_FLOATS);
#pragma unroll
            for (int k = 0; k < 4; k++) dst[tid + 512 * k] = pre[k];
        }
        __syncthreads();
        pb ^= 1;
    }
}

// ---------------- K2/K4: recurrent phases, batch-half pipelined, 7 rows/block ----
// Half A = local rows 0-3 (4), half B = local rows 4-6 (3).
// alpha: GEMM_A(t) + finalize_B(t-1). beta: GEMM_B(t) + finalize_A(t).
template<int PHASE>
__global__ void __launch_bounds__(NTH, 1) lstm_phase(
    const float* __restrict__ x,
    const float* __restrict__ wih0,
    const float* __restrict__ bih,
    const float* __restrict__ bhh,
    const float* __restrict__ fcw,
    const float* __restrict__ fcb,
    float* __restrict__ out)
{
    extern __shared__ float sm[];
    const float* Pg = (PHASE == 1) ? g_P1 : g_P2;

    const int tid = threadIdx.x;
    const int j   = tid & (HID - 1);
    const int kh  = tid >> 7;
    const int blk = blockIdx.x;
    const int bg0 = blk * RPB;
    const int valid = (BATCH - bg0 < RPB) ? (BATCH - bg0) : RPB;
    const int gb  = NSM + kh * 3;

    ulonglong2 wr[3][4];
    {
        const ulonglong2* PgD = (const ulonglong2*)Pg;
#pragma unroll
        for (int s = 0; s < 3; s++)
#pragma unroll
            for (int q = 0; q < 4; q++)
                wr[s][q] = __ldg(&PgD[(gb + s) * GATES + q * HID + j]);
    }

    float bias[4], wihr[4][DIN];
    if (PHASE == 1 && kh < 2) {
#pragma unroll
        for (int q = 0; q < 4; q++) {
            int r = q * HID + j;
            bias[q] = __ldg(bih + r) + __ldg(bhh + r);
#pragma unroll
            for (int d = 0; d < DIN; d++) wihr[q][d] = __ldg(wih0 + r * DIN + d);
        }
    }

    {
        const float4* src = (const float4*)Pg;
        float4*       dst = (float4*)(sm + OFF_WC);
        for (int i = tid; i < NSM * GATES; i += NTH) dst[i] = __ldg(src + i);
    }
    for (int i = tid; i < 1024; i += NTH) sm[OFF_HA + i] = 0.f;
    __syncthreads();

    const ulonglong2* WcD = (const ulonglong2*)(sm + OFF_WC);

    float c[2][2] = {{0.f, 0.f}, {0.f, 0.f}};
    float2 xqA[4], xqB[4];
    float  xvA[2][DIN], xvB[2][DIN];

    // -------- export helpers --------
    auto exportA = [&](float (&pr)[4][4], float (&prOwn)[4][2]) {
        float* XP = sm + OFF_XP;               // half A
        if (kh == 0) {
#pragma unroll
            for (int r = 2; r < 4; r++)
                *(float4*)(XP + r * 512 + j * 4) =
                    make_float4(pr[0][r], pr[1][r], pr[2][r], pr[3][r]);
#pragma unroll
            for (int q = 0; q < 4; q++) { prOwn[q][0] = pr[q][0]; prOwn[q][1] = pr[q][1]; }
        } else if (kh == 1) {
#pragma unroll
            for (int r = 0; r < 2; r++)
                *(float4*)(XP + r * 512 + j * 4) =
                    make_float4(pr[0][r], pr[1][r], pr[2][r], pr[3][r]);
#pragma unroll
            for (int q = 0; q < 4; q++) { prOwn[q][0] = pr[q][2]; prOwn[q][1] = pr[q][3]; }
        } else {
#pragma unroll
            for (int r = 0; r < 4; r++)
                *(float4*)(XP + 2048 + r * 512 + j * 4) =
                    make_float4(pr[0][r], pr[1][r], pr[2][r], pr[3][r]);
        }
    };
    auto exportB = [&](float (&pr)[4][3], float (&prOwn)[4][3]) {
        float* XP = sm + OFF_XP + 4096;        // half B
        if (kh == 0) {
            *(float4*)(XP + 2 * 512 + j * 4) =
                make_float4(pr[0][2], pr[1][2], pr[2][2], pr[3][2]);
#pragma unroll
            for (int q = 0; q < 4; q++) { prOwn[q][0] = pr[q][0]; prOwn[q][1] = pr[q][1]; }
        } else if (kh == 1) {
#pragma unroll
            for (int r = 0; r < 2; r++)
                *(float4*)(XP + r * 512 + j * 4) =
                    make_float4(pr[0][r], pr[1][r], pr[2][r], pr[3][r]);
#pragma unroll
            for (int q = 0; q < 4; q++) prOwn[q][0] = pr[q][2];
        } else {
#pragma unroll
            for (int r = 0; r < 3; r++)
                *(float4*)(XP + 2048 + r * 512 + j * 4) =
                    make_float4(pr[0][r], pr[1][r], pr[2][r], pr[3][r]);
        }
    };

    auto finalize_half = [&](int hoff, int half, int t, const float* prOwn0, const float* prOwn1,
                             float2 (&xq)[4], float (&xv)[2][DIN]) {
        const float* XP = sm + OFF_XP + half * 4096;
        const int nown = (kh == 0) ? 2 : (half == 0 ? 2 : 1);
#pragma unroll
        for (int r2 = 0; r2 < 2; r2++) {
            if (r2 >= nown) break;
            int rloc = 2 * kh + r2;
            const float* po = (r2 == 0) ? prOwn0 : prOwn1;
            float4 p0 = *(const float4*)(XP + rloc * 512 + j * 4);
            float4 p1 = *(const float4*)(XP + 2048 + rloc * 512 + j * 4);
            float gate[4];
            gate[0] = po[0] + p0.x + p1.x;
            gate[1] = po[1] + p0.y + p1.y;
            gate[2] = po[2] + p0.z + p1.z;
            gate[3] = po[3] + p0.w + p1.w;
            if (PHASE == 1) {
#pragma unroll
                for (int q = 0; q < 4; q++) {
                    float s = bias[q];
#pragma unroll
                    for (int d = 0; d < DIN; d++) s = fmaf(wihr[q][d], xv[r2][d], s);
                    gate[q] += s;
                }
            } else {
                gate[0] += (r2 == 0 ? xq[0].x : xq[0].y);
                gate[1] += (r2 == 0 ? xq[1].x : xq[1].y);
                gate[2] += (r2 == 0 ? xq[2].x : xq[2].y);
                gate[3] += (r2 == 0 ? xq[3].x : xq[3].y);
            }
            float cc = sigf(gate[1]) * c[half][r2] + sigf(gate[0]) * tanhf_fast(gate[2]);
            c[half][r2] = cc;
            float h = sigf(gate[3]) * tanhf_fast(cc);
            sm[hoff + rloc * HID + j] = h;
            if (PHASE == 1)
                g_h1[((size_t)(blk * S_LEN + t) * BST + half * 4 + rloc) * HID + j] = h;
        }
    };

    auto load_inputs = [&](int half, int t, float2 (&xq)[4], float (&xv)[2][DIN]) {
        if (kh >= 2) return;
        if (PHASE == 2) {
            const float* xp = g_xg1 + (size_t)(blk * S_LEN + t) * (GATES * BST);
            int off = half * 4 + 2 * kh;
#pragma unroll
            for (int q = 0; q < 4; q++)
                xq[q] = __ldg((const float2*)(xp + (q * HID + j) * BST + off));
        } else {
#pragma unroll
            for (int r2 = 0; r2 < 2; r2++) {
                int gr = bg0 + half * 4 + 2 * kh + r2;
                if (gr > BATCH - 1) gr = BATCH - 1;
                const float* xr = x + ((size_t)gr * S_LEN + t) * DIN;
#pragma unroll
                for (int d = 0; d < DIN; d++) xv[r2][d] = __ldg(xr + d);
            }
        }
    };

    float prOwnA[4][2];
    float prOwnBv[4][3];

    for (int t = 0; t < S_LEN; t++) {
        // ---- alpha: GEMM_A(t) + finalize_B(t-1) ----
        load_inputs(0, t, xqA, xvA);
        if (t > 0 && kh < 2) {
            float o0[4] = {prOwnBv[0][0], prOwnBv[1][0], prOwnBv[2][0], prOwnBv[3][0]};
            float o1[4] = {prOwnBv[0][1], prOwnBv[1][1], prOwnBv[2][1], prOwnBv[3][1]};
            finalize_half(OFF_HB, 1, t - 1, o0, o1, xqB, xvB);
        }
        {
            float prA[4][4];
            gemm_body<4>(kh, WcD, wr, gb, (const ulonglong2*)(sm + OFF_HA), j, prA);
            exportA(prA, prOwnA);
            __syncthreads();
            // ---- beta: GEMM_B(t) + finalize_A(t) ----
            load_inputs(1, t, xqB, xvB);
            if (kh < 2) {
                float o0[4] = {prOwnA[0][0], prOwnA[1][0], prOwnA[2][0], prOwnA[3][0]};
                float o1[4] = {prOwnA[0][1], prOwnA[1][1], prOwnA[2][1], prOwnA[3][1]};
                finalize_half(OFF_HA, 0, t, o0, o1, xqA, xvA);
            }
        }
        {
            float prBt[4][3];
            gemm_body<3>(kh, WcD, wr, gb, (const ulonglong2*)(sm + OFF_HB), j, prBt);
            exportB(prBt, prOwnBv);
        }
        __syncthreads();
    }
    // drain: finalize_B(511)
    if (kh < 2) {
        float o0[4] = {prOwnBv[0][0], prOwnBv[1][0], prOwnBv[2][0], prOwnBv[3][0]};
        float o1[4] = {prOwnBv[0][1], prOwnBv[1][1], prOwnBv[2][1], prOwnBv[3][1]};
        finalize_half(OFF_HB, 1, S_LEN - 1, o0, o1, xqB, xvB);
    }
    __syncthreads();

    if (PHASE == 2 && tid < 224) {
        int w = tid >> 5, lane = tid & 31;
        if (w < valid) {
            const float* hrow = sm + (w < 4 ? OFF_HA + w * HID : OFF_HB + (w - 4) * HID);
            float s = 0.f;
#pragma unroll
            for (int m = 0; m < HID; m += 32)
                s += hrow[lane + m] * __ldg(fcw + lane + m);
#pragma unroll
            for (int o = 16; o > 0; o >>= 1) s += __shfl_down_sync(0xffffffffu, s, o);
            if (lane == 0) out[bg0 + w] = s + __ldg(fcb);
        }
    }
}

// ---------------- launch ----------------
extern "C" void kernel_launch(void* const* d_in, const int* in_sizes, int n_in,
                              void* d_out, int out_size) {
    const float* x    = (const float*)d_in[0];
    const float* wih0 = (const float*)d_in[1];
    const float* whh0 = (const float*)d_in[2];
    const float* bih0 = (const float*)d_in[3];
    const float* bhh0 = (const float*)d_in[4];
    const float* wih1 = (const float*)d_in[5];
    const float* whh1 = (const float*)d_in[6];
    const float* bih1 = (const float*)d_in[7];
    const float* bhh1 = (const float*)d_in[8];
    const float* fcw  = (const float*)d_in[9];
    const float* fcb  = (const float*)d_in[10];
    float* out = (float*)d_out;
    (void)in_sizes; (void)n_in; (void)out_size;

    cudaFuncSetAttribute(lstm_phase<1>, cudaFuncAttributeMaxDynamicSharedMemorySize, PH_SMEM_BYTES);
    cudaFuncSetAttribute(lstm_phase<2>, cudaFuncAttributeMaxDynamicSharedMemorySize, PH_SMEM_BYTES);
    cudaFuncSetAttribute(xg1_gemm,      cudaFuncAttributeMaxDynamicSharedMemorySize, GM_SMEM_BYTES);

    pack_kernel<<<(GATES * HID + 255) / 256, 256>>>(whh0, whh1, wih1);
    lstm_phase<1><<<NBLK, NTH, PH_SMEM_BYTES>>>(x, wih0, bih0, bhh0, fcw, fcb, out);
    xg1_gemm<<<dim3(2, 74, 4), GM_THREADS, GM_SMEM_BYTES>>>(bih1, bhh1);
    lstm_phase<2><<<NBLK, NTH, PH_SMEM_BYTES>>>(x, wih0, bih1, bhh1, fcw, fcb, out);
}

// round 13
// speedup vs baseline: 1.2340x; 1.0408x over previous
#include <cuda_runtime.h>

// ---------------- problem constants ----------------
#define S_LEN  512
#define DIN    5
#define HID    128
#define GATES  512
#define BATCH  1024
#define NBLK   147     // recurrence blocks: 146 x 7 rows + 1 x 2 rows
#define RPB    7       // rows per block (logical)
#define BST    8       // row stride in g_h1 / g_xg1 (padded)
#define NG     32      // k-groups (of 4) per 128-wide K
#define NSM    23      // k-groups cached in smem (rest in registers)
#define NTH    384     // phase threads = 128 j x 3 kh

// phase smem layout (float offsets)
#define OFF_WC  0
#define OFF_HA  (NSM*GATES*4)            // 47104 : hA [4][128]
#define OFF_HB  (OFF_HA + 512)           // 47616 : hB [3][128] (512 reserved)
#define OFF_XP  (OFF_HB + 512)           // 48128 : [2 half][2 slot][4 r][128 j][4 q]
#define PH_SMEM_BYTES ((OFF_XP + 8192)*4)   // 225280

// tf32 mma gemm smem: A[128][132] + B[128][132] tf32 (C staging reuses A region)
#define TG_THREADS 256
#define TG_PAD 132
#define TG_B_OFF (128*TG_PAD)            // 16896 floats
#define TG_SMEM_BYTES (2*128*TG_PAD*4)   // 135168 B

// ---------------- global scratch (static) ----------------
__device__ __align__(16) float g_P1[NG * GATES * 4];   // packed w_hh0
__device__ __align__(16) float g_P2[NG * GATES * 4];   // packed w_hh1
__device__ __align__(16) float g_h1 [(size_t)NBLK * S_LEN * BST * HID];    // [blk][t][b8][j]
__device__ __align__(16) float g_xg1[(size_t)NBLK * S_LEN * GATES * BST];  // [blk][t][col][b8]

// ---------------- helpers ----------------
typedef unsigned long long u64;
__device__ __forceinline__ void ffma2(u64 &d, u64 a, u64 b) {
    asm("fma.rn.f32x2 %0, %1, %2, %0;" : "+l"(d) : "l"(a), "l"(b));
}
__device__ __forceinline__ float flo(u64 v) { return __uint_as_float((unsigned)v); }
__device__ __forceinline__ float fhi(u64 v) { return __uint_as_float((unsigned)(v >> 32)); }
__device__ __forceinline__ float sigf(float x) {
    return __fdividef(1.0f, 1.0f + __expf(-x));
}
__device__ __forceinline__ float tanhf_fast(float x) {
    float e = __expf(2.0f * x);
    return 1.0f - __fdividef(2.0f, e + 1.0f);
}
__device__ __forceinline__ unsigned f2tf32(float f) {
    unsigned r;
    asm("cvt.rna.tf32.f32 %0, %1;" : "=r"(r) : "f"(f));
    return r;
}
__device__ __forceinline__ void mma_tf32(float (&d)[4], const unsigned (&a)[4],
                                         const unsigned (&b)[2]) {
    asm("mma.sync.aligned.m16n8k8.row.col.f32.tf32.tf32.f32 "
        "{%0,%1,%2,%3}, {%4,%5,%6,%7}, {%8,%9}, {%0,%1,%2,%3};"
        : "+f"(d[0]), "+f"(d[1]), "+f"(d[2]), "+f"(d[3])
        : "r"(a[0]), "r"(a[1]), "r"(a[2]), "r"(a[3]), "r"(b[0]), "r"(b[1]));
}

// smem-group accumulation over NB batch rows (phase kernels)
template<int G0, int G1, int NB>
__device__ __forceinline__ void accum_smem(u64 (&acc)[4][NB],
                                           const ulonglong2* __restrict__ W,
                                           const ulonglong2* __restrict__ H,
                                           int j) {
#pragma unroll
    for (int g = G0; g < G1; g++) {
        ulonglong2 w[4];
#pragma unroll
        for (int q = 0; q < 4; q++) w[q] = W[g * GATES + q * HID + j];
#pragma unroll
        for (int b = 0; b < NB; b++) {
            ulonglong2 hv = H[b * 32 + g];
#pragma unroll
            for (int q = 0; q < 4; q++) {
                ffma2(acc[q][b], w[q].x, hv.x);
                ffma2(acc[q][b], w[q].y, hv.y);
            }
        }
    }
}

template<int NB>
__device__ __forceinline__ void gemm_body(int kh, const ulonglong2* __restrict__ WcD,
                                          const ulonglong2 (&wr)[3][4], int gb,
                                          const ulonglong2* __restrict__ H, int j,
                                          float (&pr)[4][NB]) {
    u64 acc[4][NB];
#pragma unroll
    for (int q = 0; q < 4; q++)
#pragma unroll
        for (int b = 0; b < NB; b++) acc[q][b] = 0ull;
    if (kh == 0)      accum_smem<0,  7,  NB>(acc, WcD, H, j);
    else if (kh == 1) accum_smem<7,  14, NB>(acc, WcD, H, j);
    else              accum_smem<14, NSM, NB>(acc, WcD, H, j);
#pragma unroll
    for (int s = 0; s < 3; s++) {
#pragma unroll
        for (int b = 0; b < NB; b++) {
            ulonglong2 hv = H[b * 32 + gb + s];
#pragma unroll
            for (int q = 0; q < 4; q++) {
                ffma2(acc[q][b], wr[s][q].x, hv.x);
                ffma2(acc[q][b], wr[s][q].y, hv.y);
            }
        }
    }
#pragma unroll
    for (int q = 0; q < 4; q++)
#pragma unroll
        for (int b = 0; b < NB; b++) pr[q][b] = flo(acc[q][b]) + fhi(acc[q][b]);
}

// ---------------- K1: pack weights (recurrence only) ----------------
__global__ void pack_kernel(const float* __restrict__ whh0,
                            const float* __restrict__ whh1) {
    int i = blockIdx.x * blockDim.x + threadIdx.x;
    if (i >= GATES * HID) return;
    int col = i / HID, k = i % HID;
    int g = k >> 2, dk = k & 3;
    size_t o = ((size_t)g * GATES + col) * 4 + dk;
    g_P1[o] = whh0[col * HID + k];
    g_P2[o] = whh1[col * HID + k];
}

// ---------------- K3: xg1 = h1 @ w_ih1^T + biases  (tf32 tensor-core) ----------------
// grid (128, NBLK): x = nt(0..3) | mt(0..31)<<2.  CTA tile: M=128 (16 t x 8 b), N=128, K=128.
// 8 warps in 4m x 2n grid; warp tile 32x64 via m16n8k8 (2 msub x 8 nsub).
__global__ void __launch_bounds__(TG_THREADS, 1) xg1_mma(
    const float* __restrict__ wih1,
    const float* __restrict__ bih1,
    const float* __restrict__ bhh1)
{
    extern __shared__ float smf[];
    unsigned* As = (unsigned*)smf;               // [128][132] tf32 (rows = m, cols = k)
    unsigned* Bs = (unsigned*)(smf + TG_B_OFF);  // [128][132] tf32 (rows = n, cols = k)

    const int tid  = threadIdx.x;
    const int lane = tid & 31;
    const int wid  = tid >> 5;         // 0..7
    const int wm   = wid >> 1;         // 0..3 -> m offset 32*wm
    const int wn   = wid & 1;          // 0..1 -> n offset 64*wn
    const int nt   = blockIdx.x & 3;
    const int mt   = blockIdx.x >> 2;  // 0..31
    const int blk  = blockIdx.y;
    const int t0   = mt * 16;
    const int n0   = nt * 128;

    // stage A (h1 rows m = t*8+b for t in [t0,t0+16)) and B (wih1 rows n0..n0+127), cvt to tf32
    {
        const float4* Ag = (const float4*)(g_h1 + (size_t)(blk * S_LEN + t0) * (BST * HID));
        const float4* Bg = (const float4*)(wih1 + (size_t)n0 * HID);
        for (int i = tid; i < 128 * 32; i += TG_THREADS) {   // 32 float4 per row
            int row = i >> 5, c4 = i & 31;
            float4 av = __ldg(Ag + i);
            float4 bv = __ldg(Bg + i);
            unsigned* ad = As + row * TG_PAD + c4 * 4;
            ad[0] = f2tf32(av.x); ad[1] = f2tf32(av.y); ad[2] = f2tf32(av.z); ad[3] = f2tf32(av.w);
            unsigned* bd = Bs + row * TG_PAD + c4 * 4;
            bd[0] = f2tf32(bv.x); bd[1] = f2tf32(bv.y); bd[2] = f2tf32(bv.z); bd[3] = f2tf32(bv.w);
        }
    }
    __syncthreads();

    const int g   = lane >> 2;   // 0..7
    const int tig = lane & 3;    // 0..3

    float acc[2][8][4];
#pragma unroll
    for (int ms = 0; ms < 2; ms++)
#pragma unroll
        for (int ns = 0; ns < 8; ns++)
#pragma unroll
            for (int e = 0; e < 4; e++) acc[ms][ns][e] = 0.f;

#pragma unroll 2
    for (int ks = 0; ks < 16; ks++) {
        const int k0 = ks * 8;
        unsigned a[2][4], b[8][2];
#pragma unroll
        for (int ms = 0; ms < 2; ms++) {
            int r0 = wm * 32 + ms * 16 + g;
            a[ms][0] = As[r0 * TG_PAD + k0 + tig];
            a[ms][1] = As[(r0 + 8) * TG_PAD + k0 + tig];
            a[ms][2] = As[r0 * TG_PAD + k0 + tig + 4];
            a[ms][3] = As[(r0 + 8) * TG_PAD + k0 + tig + 4];
        }
#pragma unroll
        for (int ns = 0; ns < 8; ns++) {
            int nb = wn * 64 + ns * 8 + g;
            b[ns][0] = Bs[nb * TG_PAD + k0 + tig];
            b[ns][1] = Bs[nb * TG_PAD + k0 + tig + 4];
        }
#pragma unroll
        for (int ms = 0; ms < 2; ms++)
#pragma unroll
            for (int ns = 0; ns < 8; ns++)
                mma_tf32(acc[ms][ns], a[ms], b[ns]);
    }
    __syncthreads();   // done reading As/Bs; reuse As region as C staging

    // stage C: layout [tloc(16)][n(128)][b(8)] floats = 16384 (fits in A region 16896)
    float* Cs = smf;
#pragma unroll
    for (int ms = 0; ms < 2; ms++) {
#pragma unroll
        for (int ns = 0; ns < 8; ns++) {
            int r0 = wm * 32 + ms * 16 + g;
            int r2 = r0 + 8;
            int c0 = wn * 64 + ns * 8 + 2 * tig;
            Cs[(r0 >> 3) * 1024 + c0 * 8 + (r0 & 7)]       = acc[ms][ns][0];
            Cs[(r0 >> 3) * 1024 + (c0 + 1) * 8 + (r0 & 7)] = acc[ms][ns][1];
            Cs[(r2 >> 3) * 1024 + c0 * 8 + (r2 & 7)]       = acc[ms][ns][2];
            Cs[(r2 >> 3) * 1024 + (c0 + 1) * 8 + (r2 & 7)] = acc[ms][ns][3];
        }
    }
    __syncthreads();

    // coalesced store with bias add: 4096 float4, [t][n][b] matches g_xg1 [col][b8]
    for (int i = tid; i < 4096; i += TG_THREADS) {
        int tloc = i >> 8;          // 256 float4 per t
        int rest = i & 255;         // n*2 + (b>>2)
        int n = rest >> 1;
        float4 v = ((const float4*)Cs)[i];
        float bias = __ldg(bih1 + n0 + n) + __ldg(bhh1 + n0 + n);
        v.x += bias; v.y += bias; v.z += bias; v.w += bias;
        ((float4*)(g_xg1 + ((size_t)((blk * S_LEN + t0 + tloc) * GATES) + n0) * BST))[rest] = v;
    }
}

// ---------------- K2/K4: recurrent phases, batch-half pipelined, 7 rows/block ----
// Half A = local rows 0-3 (4), half B = local rows 4-6 (3).
// alpha: GEMM_A(t) + finalize_B(t-1). beta: GEMM_B(t) + finalize_A(t).
template<int PHASE>
__global__ void __launch_bounds__(NTH, 1) lstm_phase(
    const float* __restrict__ x,
    const float* __restrict__ wih0,
    const float* __restrict__ bih,
    const float* __restrict__ bhh,
    const float* __restrict__ fcw,
    const float* __restrict__ fcb,
    float* __restrict__ out)
{
    extern __shared__ float sm[];
    const float* Pg = (PHASE == 1) ? g_P1 : g_P2;

    const int tid = threadIdx.x;
    const int j   = tid & (HID - 1);
    const int kh  = tid >> 7;
    const int blk = blockIdx.x;
    const int bg0 = blk * RPB;
    const int valid = (BATCH - bg0 < RPB) ? (BATCH - bg0) : RPB;
    const int gb  = NSM + kh * 3;

    ulonglong2 wr[3][4];
    {
        const ulonglong2* PgD = (const ulonglong2*)Pg;
#pragma unroll
        for (int s = 0; s < 3; s++)
#pragma unroll
            for (int q = 0; q < 4; q++)
                wr[s][q] = __ldg(&PgD[(gb + s) * GATES + q * HID + j]);
    }

    float bias[4], wihr[4][DIN];
    if (PHASE == 1 && kh < 2) {
#pragma unroll
        for (int q = 0; q < 4; q++) {
            int r = q * HID + j;
            bias[q] = __ldg(bih + r) + __ldg(bhh + r);
#pragma unroll
            for (int d = 0; d < DIN; d++) wihr[q][d] = __ldg(wih0 + r * DIN + d);
        }
    }

    {
        const float4* src = (const float4*)Pg;
        float4*       dst = (float4*)(sm + OFF_WC);
        for (int i = tid; i < NSM * GATES; i += NTH) dst[i] = __ldg(src + i);
    }
    for (int i = tid; i < 1024; i += NTH) sm[OFF_HA + i] = 0.f;
    __syncthreads();

    const ulonglong2* WcD = (const ulonglong2*)(sm + OFF_WC);

    float c[2][2] = {{0.f, 0.f}, {0.f, 0.f}};
    float2 xqA[4], xqB[4];
    float  xvA[2][DIN], xvB[2][DIN];

    // -------- export helpers --------
    auto exportA = [&](float (&pr)[4][4], float (&prOwn)[4][2]) {
        float* XP = sm + OFF_XP;               // half A
        if (kh == 0) {
#pragma unroll
            for (int r = 2; r < 4; r++)
                *(float4*)(XP + r * 512 + j * 4) =
                    make_float4(pr[0][r], pr[1][r], pr[2][r], pr[3][r]);
#pragma unroll
            for (int q = 0; q < 4; q++) { prOwn[q][0] = pr[q][0]; prOwn[q][1] = pr[q][1]; }
        } else if (kh == 1) {
#pragma unroll
            for (int r = 0; r < 2; r++)
                *(float4*)(XP + r * 512 + j * 4) =
                    make_float4(pr[0][r], pr[1][r], pr[2][r], pr[3][r]);
#pragma unroll
            for (int q = 0; q < 4; q++) { prOwn[q][0] = pr[q][2]; prOwn[q][1] = pr[q][3]; }
        } else {
#pragma unroll
            for (int r = 0; r < 4; r++)
                *(float4*)(XP + 2048 + r * 512 + j * 4) =
                    make_float4(pr[0][r], pr[1][r], pr[2][r], pr[3][r]);
        }
    };
    auto exportB = [&](float (&pr)[4][3], float (&prOwn)[4][3]) {
        float* XP = sm + OFF_XP + 4096;        // half B
        if (kh == 0) {
            *(float4*)(XP + 2 * 512 + j * 4) =
                make_float4(pr[0][2], pr[1][2], pr[2][2], pr[3][2]);
#pragma unroll
            for (int q = 0; q < 4; q++) { prOwn[q][0] = pr[q][0]; prOwn[q][1] = pr[q][1]; }
        } else if (kh == 1) {
#pragma unroll
            for (int r = 0; r < 2; r++)
                *(float4*)(XP + r * 512 + j * 4) =
                    make_float4(pr[0][r], pr[1][r], pr[2][r], pr[3][r]);
#pragma unroll
            for (int q = 0; q < 4; q++) prOwn[q][0] = pr[q][2];
        } else {
#pragma unroll
            for (int r = 0; r < 3; r++)
                *(float4*)(XP + 2048 + r * 512 + j * 4) =
                    make_float4(pr[0][r], pr[1][r], pr[2][r], pr[3][r]);
        }
    };

    auto finalize_half = [&](int hoff, int half, int t, const float* prOwn0, const float* prOwn1,
                             float2 (&xq)[4], float (&xv)[2][DIN]) {
        const float* XP = sm + OFF_XP + half * 4096;
        const int nown = (kh == 0) ? 2 : (half == 0 ? 2 : 1);
#pragma unroll
        for (int r2 = 0; r2 < 2; r2++) {
            if (r2 >= nown) break;
            int rloc = 2 * kh + r2;
            const float* po = (r2 == 0) ? prOwn0 : prOwn1;
            float4 p0 = *(const float4*)(XP + rloc * 512 + j * 4);
            float4 p1 = *(const float4*)(XP + 2048 + rloc * 512 + j * 4);
            float gate[4];
            gate[0] = po[0] + p0.x + p1.x;
            gate[1] = po[1] + p0.y + p1.y;
            gate[2] = po[2] + p0.z + p1.z;
            gate[3] = po[3] + p0.w + p1.w;
            if (PHASE == 1) {
#pragma unroll
                for (int q = 0; q < 4; q++) {
                    float s = bias[q];
#pragma unroll
                    for (int d = 0; d < DIN; d++) s = fmaf(wihr[q][d], xv[r2][d], s);
                    gate[q] += s;
                }
            } else {
                gate[0] += (r2 == 0 ? xq[0].x : xq[0].y);
                gate[1] += (r2 == 0 ? xq[1].x : xq[1].y);
                gate[2] += (r2 == 0 ? xq[2].x : xq[2].y);
                gate[3] += (r2 == 0 ? xq[3].x : xq[3].y);
            }
            float cc = sigf(gate[1]) * c[half][r2] + sigf(gate[0]) * tanhf_fast(gate[2]);
            c[half][r2] = cc;
            float h = sigf(gate[3]) * tanhf_fast(cc);
            sm[hoff + rloc * HID + j] = h;
            if (PHASE == 1)
                g_h1[((size_t)(blk * S_LEN + t) * BST + half * 4 + rloc) * HID + j] = h;
        }
    };

    auto load_inputs = [&](int half, int t, float2 (&xq)[4], float (&xv)[2][DIN]) {
        if (kh >= 2) return;
        if (PHASE == 2) {
            const float* xp = g_xg1 + (size_t)(blk * S_LEN + t) * (GATES * BST);
            int off = half * 4 + 2 * kh;
#pragma unroll
            for (int q = 0; q < 4; q++)
                xq[q] = __ldg((const float2*)(xp + (q * HID + j) * BST + off));
        } else {
#pragma unroll
            for (int r2 = 0; r2 < 2; r2++) {
                int gr = bg0 + half * 4 + 2 * kh + r2;
                if (gr > BATCH - 1) gr = BATCH - 1;
                const float* xr = x + ((size_t)gr * S_LEN + t) * DIN;
#pragma unroll
                for (int d = 0; d < DIN; d++) xv[r2][d] = __ldg(xr + d);
            }
        }
    };

    float prOwnA[4][2];
    float prOwnBv[4][3];

    for (int t = 0; t < S_LEN; t++) {
        // ---- alpha: GEMM_A(t) + finalize_B(t-1) ----
        load_inputs(0, t, xqA, xvA);
        if (t > 0 && kh < 2) {
            float o0[4] = {prOwnBv[0][0], prOwnBv[1][0], prOwnBv[2][0], prOwnBv[3][0]};
            float o1[4] = {prOwnBv[0][1], prOwnBv[1][1], prOwnBv[2][1], prOwnBv[3][1]};
            finalize_half(OFF_HB, 1, t - 1, o0, o1, xqB, xvB);
        }
        {
            float prA[4][4];
            gemm_body<4>(kh, WcD, wr, gb, (const ulonglong2*)(sm + OFF_HA), j, prA);
            exportA(prA, prOwnA);
            __syncthreads();
            // ---- beta: GEMM_B(t) + finalize_A(t) ----
            load_inputs(1, t, xqB, xvB);
            if (kh < 2) {
                float o0[4] = {prOwnA[0][0], prOwnA[1][0], prOwnA[2][0], prOwnA[3][0]};
                float o1[4] = {prOwnA[0][1], prOwnA[1][1], prOwnA[2][1], prOwnA[3][1]};
                finalize_half(OFF_HA, 0, t, o0, o1, xqA, xvA);
            }
        }
        {
            float prBt[4][3];
            gemm_body<3>(kh, WcD, wr, gb, (const ulonglong2*)(sm + OFF_HB), j, prBt);
            exportB(prBt, prOwnBv);
        }
        __syncthreads();
    }
    // drain: finalize_B(511)
    if (kh < 2) {
        float o0[4] = {prOwnBv[0][0], prOwnBv[1][0], prOwnBv[2][0], prOwnBv[3][0]};
        float o1[4] = {prOwnBv[0][1], prOwnBv[1][1], prOwnBv[2][1], prOwnBv[3][1]};
        finalize_half(OFF_HB, 1, S_LEN - 1, o0, o1, xqB, xvB);
    }
    __syncthreads();

    if (PHASE == 2 && tid < 224) {
        int w = tid >> 5, lane = tid & 31;
        if (w < valid) {
            const float* hrow = sm + (w < 4 ? OFF_HA + w * HID : OFF_HB + (w - 4) * HID);
            float s = 0.f;
#pragma unroll
            for (int m = 0; m < HID; m += 32)
                s += hrow[lane + m] * __ldg(fcw + lane + m);
#pragma unroll
            for (int o = 16; o > 0; o >>= 1) s += __shfl_down_sync(0xffffffffu, s, o);
            if (lane == 0) out[bg0 + w] = s + __ldg(fcb);
        }
    }
}

// ---------------- launch ----------------
extern "C" void kernel_launch(void* const* d_in, const int* in_sizes, int n_in,
                              void* d_out, int out_size) {
    const float* x    = (const float*)d_in[0];
    const float* wih0 = (const float*)d_in[1];
    const float* whh0 = (const float*)d_in[2];
    const float* bih0 = (const float*)d_in[3];
    const float* bhh0 = (const float*)d_in[4];
    const float* wih1 = (const float*)d_in[5];
    const float* whh1 = (const float*)d_in[6];
    const float* bih1 = (const float*)d_in[7];
    const float* bhh1 = (const float*)d_in[8];
    const float* fcw  = (const float*)d_in[9];
    const float* fcb  = (const float*)d_in[10];
    float* out = (float*)d_out;
    (void)in_sizes; (void)n_in; (void)out_size;

    cudaFuncSetAttribute(lstm_phase<1>, cudaFuncAttributeMaxDynamicSharedMemorySize, PH_SMEM_BYTES);
    cudaFuncSetAttribute(lstm_phase<2>, cudaFuncAttributeMaxDynamicSharedMemorySize, PH_SMEM_BYTES);
    cudaFuncSetAttribute(xg1_mma,       cudaFuncAttributeMaxDynamicSharedMemorySize, TG_SMEM_BYTES);

    pack_kernel<<<(GATES * HID + 255) / 256, 256>>>(whh0, whh1);
    lstm_phase<1><<<NBLK, NTH, PH_SMEM_BYTES>>>(x, wih0, bih0, bhh0, fcw, fcb, out);
    xg1_mma<<<dim3(128, NBLK), TG_THREADS, TG_SMEM_BYTES>>>(wih1, bih1, bhh1);
    lstm_phase<2><<<NBLK, NTH, PH_SMEM_BYTES>>>(x, wih0, bih1, bhh1, fcw, fcb, out);
}

// round 14
// speedup vs baseline: 1.2483x; 1.0115x over previous
#include <cuda_runtime.h>

// ---------------- problem constants ----------------
#define S_LEN  512
#define DIN    5
#define HID    128
#define GATES  512
#define BATCH  1024
#define NBLK   147     // recurrence blocks: 146 x 7 rows + 1 x 2 rows
#define RPB    7       // rows per block (logical)
#define BST    8       // row stride in g_h1 / g_xg1 (padded)
#define NG     32      // k-groups (of 4) per 128-wide K
#define NSM    23      // k-groups cached in smem (rest in registers)
#define NTH    384     // phase threads = 128 j x 3 kh

// phase smem layout (float offsets)
#define OFF_WC  0
#define OFF_HA  (NSM*GATES*4)            // 47104 : hA [4][128]
#define OFF_HB  (OFF_HA + 512)           // 47616 : hB [3][128] (512 reserved)
#define OFF_XP  (OFF_HB + 512)           // 48128 : [2 half][2 slot][4 r][128 j][4 q]
#define PH_SMEM_BYTES ((OFF_XP + 8192)*4)   // 225280

// tf32 mma gemm smem: A[128][132] + B[64][132] (C staging reuses A region)
#define TG_THREADS 256
#define TG_PAD 132
#define TG_A_FLOATS (128*TG_PAD)         // 16896
#define TG_B_FLOATS (64*TG_PAD)          // 8448
#define TG_SMEM_BYTES ((TG_A_FLOATS + TG_B_FLOATS)*4)   // 101376 -> 2 CTAs/SM

// ---------------- global scratch (static) ----------------
__device__ __align__(16) float g_P1[NG * GATES * 4];   // packed w_hh0
__device__ __align__(16) float g_P2[NG * GATES * 4];   // packed w_hh1
__device__ __align__(16) float g_h1 [(size_t)NBLK * S_LEN * BST * HID];    // [blk][t][b8][j] (tf32-rounded)
__device__ __align__(16) float g_xg1[(size_t)NBLK * S_LEN * GATES * BST];  // [blk][t][col][b8]

// ---------------- helpers ----------------
typedef unsigned long long u64;
__device__ __forceinline__ void ffma2(u64 &d, u64 a, u64 b) {
    asm("fma.rn.f32x2 %0, %1, %2, %0;" : "+l"(d) : "l"(a), "l"(b));
}
__device__ __forceinline__ float flo(u64 v) { return __uint_as_float((unsigned)v); }
__device__ __forceinline__ float fhi(u64 v) { return __uint_as_float((unsigned)(v >> 32)); }
__device__ __forceinline__ float sigf(float x) {
    return __fdividef(1.0f, 1.0f + __expf(-x));
}
__device__ __forceinline__ float tanhf_fast(float x) {
    float e = __expf(2.0f * x);
    return 1.0f - __fdividef(2.0f, e + 1.0f);
}
__device__ __forceinline__ unsigned f2tf32(float f) {
    unsigned r;
    asm("cvt.rna.tf32.f32 %0, %1;" : "=r"(r) : "f"(f));
    return r;
}
__device__ __forceinline__ void mma_tf32(float (&d)[4], const unsigned (&a)[4],
                                         const unsigned (&b)[2]) {
    asm("mma.sync.aligned.m16n8k8.row.col.f32.tf32.tf32.f32 "
        "{%0,%1,%2,%3}, {%4,%5,%6,%7}, {%8,%9}, {%0,%1,%2,%3};"
        : "+f"(d[0]), "+f"(d[1]), "+f"(d[2]), "+f"(d[3])
        : "r"(a[0]), "r"(a[1]), "r"(a[2]), "r"(a[3]), "r"(b[0]), "r"(b[1]));
}

// smem-group accumulation over NB batch rows (phase kernels)
template<int G0, int G1, int NB>
__device__ __forceinline__ void accum_smem(u64 (&acc)[4][NB],
                                           const ulonglong2* __restrict__ W,
                                           const ulonglong2* __restrict__ H,
                                           int j) {
#pragma unroll
    for (int g = G0; g < G1; g++) {
        ulonglong2 w[4];
#pragma unroll
        for (int q = 0; q < 4; q++) w[q] = W[g * GATES + q * HID + j];
#pragma unroll
        for (int b = 0; b < NB; b++) {
            ulonglong2 hv = H[b * 32 + g];
#pragma unroll
            for (int q = 0; q < 4; q++) {
                ffma2(acc[q][b], w[q].x, hv.x);
                ffma2(acc[q][b], w[q].y, hv.y);
            }
        }
    }
}

template<int NB>
__device__ __forceinline__ void gemm_body(int kh, const ulonglong2* __restrict__ WcD,
                                          const ulonglong2 (&wr)[3][4], int gb,
                                          const ulonglong2* __restrict__ H, int j,
                                          float (&pr)[4][NB]) {
    u64 acc[4][NB];
#pragma unroll
    for (int q = 0; q < 4; q++)
#pragma unroll
        for (int b = 0; b < NB; b++) acc[q][b] = 0ull;
    if (kh == 0)      accum_smem<0,  7,  NB>(acc, WcD, H, j);
    else if (kh == 1) accum_smem<7,  14, NB>(acc, WcD, H, j);
    else              accum_smem<14, NSM, NB>(acc, WcD, H, j);
#pragma unroll
    for (int s = 0; s < 3; s++) {
#pragma unroll
        for (int b = 0; b < NB; b++) {
            ulonglong2 hv = H[b * 32 + gb + s];
#pragma unroll
            for (int q = 0; q < 4; q++) {
                ffma2(acc[q][b], wr[s][q].x, hv.x);
                ffma2(acc[q][b], wr[s][q].y, hv.y);
            }
        }
    }
#pragma unroll
    for (int q = 0; q < 4; q++)
#pragma unroll
        for (int b = 0; b < NB; b++) pr[q][b] = flo(acc[q][b]) + fhi(acc[q][b]);
}

// ---------------- K1: pack weights (recurrence only) ----------------
__global__ void pack_kernel(const float* __restrict__ whh0,
                            const float* __restrict__ whh1) {
    int i = blockIdx.x * blockDim.x + threadIdx.x;
    if (i >= GATES * HID) return;
    int col = i / HID, k = i % HID;
    int g = k >> 2, dk = k & 3;
    size_t o = ((size_t)g * GATES + col) * 4 + dk;
    g_P1[o] = whh0[col * HID + k];
    g_P2[o] = whh1[col * HID + k];
}

// ---------------- K3: xg1 = h1 @ w_ih1^T + biases  (tf32 tensor-core) ----------------
// grid (256, NBLK): x = nt(0..7) | mt(0..31)<<3.  CTA tile: M=128 (16 t x 8 b), N=64, K=128.
// 8 warps in 4m x 2n grid; warp tile 32x32 via m16n8k8 (2 msub x 4 nsub). 2 CTAs/SM.
__global__ void __launch_bounds__(TG_THREADS, 2) xg1_mma(
    const float* __restrict__ wih1,
    const float* __restrict__ bih1,
    const float* __restrict__ bhh1)
{
    extern __shared__ float smf[];
    unsigned* As = (unsigned*)smf;                  // [128][132] tf32 (rows = m, cols = k)
    unsigned* Bs = (unsigned*)(smf + TG_A_FLOATS);  // [64][132]  tf32 (rows = n, cols = k)

    const int tid  = threadIdx.x;
    const int lane = tid & 31;
    const int wid  = tid >> 5;         // 0..7
    const int wm   = wid >> 1;         // 0..3 -> m offset 32*wm
    const int wn   = wid & 1;          // 0..1 -> n offset 32*wn
    const int nt   = blockIdx.x & 7;
    const int mt   = blockIdx.x >> 3;  // 0..31
    const int blk  = blockIdx.y;
    const int t0   = mt * 16;
    const int n0   = nt * 64;

    // stage A (h1 already tf32-rounded: pure copy) and B (cvt to tf32)
    {
        const float4* Ag = (const float4*)(g_h1 + (size_t)(blk * S_LEN + t0) * (BST * HID));
        for (int i = tid; i < 128 * 32; i += TG_THREADS) {   // 32 float4 per row
            int row = i >> 5, c4 = i & 31;
            float4 av = __ldg(Ag + i);
            *(float4*)((float*)As + row * TG_PAD + c4 * 4) = av;
        }
        const float4* Bg = (const float4*)(wih1 + (size_t)n0 * HID);
        for (int i = tid; i < 64 * 32; i += TG_THREADS) {
            int row = i >> 5, c4 = i & 31;
            float4 bv = __ldg(Bg + i);
            unsigned* bd = Bs + row * TG_PAD + c4 * 4;
            bd[0] = f2tf32(bv.x); bd[1] = f2tf32(bv.y); bd[2] = f2tf32(bv.z); bd[3] = f2tf32(bv.w);
        }
    }
    __syncthreads();

    const int g   = lane >> 2;   // 0..7
    const int tig = lane & 3;    // 0..3

    float acc[2][4][4];
#pragma unroll
    for (int ms = 0; ms < 2; ms++)
#pragma unroll
        for (int ns = 0; ns < 4; ns++)
#pragma unroll
            for (int e = 0; e < 4; e++) acc[ms][ns][e] = 0.f;

#pragma unroll 2
    for (int ks = 0; ks < 16; ks++) {
        const int k0 = ks * 8;
        unsigned a[2][4], b[4][2];
#pragma unroll
        for (int ms = 0; ms < 2; ms++) {
            int r0 = wm * 32 + ms * 16 + g;
            a[ms][0] = As[r0 * TG_PAD + k0 + tig];
            a[ms][1] = As[(r0 + 8) * TG_PAD + k0 + tig];
            a[ms][2] = As[r0 * TG_PAD + k0 + tig + 4];
            a[ms][3] = As[(r0 + 8) * TG_PAD + k0 + tig + 4];
        }
#pragma unroll
        for (int ns = 0; ns < 4; ns++) {
            int nb = wn * 32 + ns * 8 + g;
            b[ns][0] = Bs[nb * TG_PAD + k0 + tig];
            b[ns][1] = Bs[nb * TG_PAD + k0 + tig + 4];
        }
#pragma unroll
        for (int ms = 0; ms < 2; ms++)
#pragma unroll
            for (int ns = 0; ns < 4; ns++)
                mma_tf32(acc[ms][ns], a[ms], b[ns]);
    }
    __syncthreads();   // done reading As/Bs; reuse As region as C staging

    // stage C: layout [tloc(16)][n(64)][b(8)] floats = 8192 (fits in A region 16896)
    float* Cs = smf;
#pragma unroll
    for (int ms = 0; ms < 2; ms++) {
#pragma unroll
        for (int ns = 0; ns < 4; ns++) {
            int r0 = wm * 32 + ms * 16 + g;
            int r2 = r0 + 8;
            int c0 = wn * 32 + ns * 8 + 2 * tig;
            Cs[(r0 >> 3) * 512 + c0 * 8 + (r0 & 7)]       = acc[ms][ns][0];
            Cs[(r0 >> 3) * 512 + (c0 + 1) * 8 + (r0 & 7)] = acc[ms][ns][1];
            Cs[(r2 >> 3) * 512 + c0 * 8 + (r2 & 7)]       = acc[ms][ns][2];
            Cs[(r2 >> 3) * 512 + (c0 + 1) * 8 + (r2 & 7)] = acc[ms][ns][3];
        }
    }
    __syncthreads();

    // coalesced store with bias add: 2048 float4, [t][n][b] matches g_xg1 [col][b8]
    for (int i = tid; i < 2048; i += TG_THREADS) {
        int tloc = i >> 7;          // 128 float4 per t
        int rest = i & 127;         // n*2 + (b>>2)
        int n = rest >> 1;
        float4 v = ((const float4*)Cs)[i];
        float bias = __ldg(bih1 + n0 + n) + __ldg(bhh1 + n0 + n);
        v.x += bias; v.y += bias; v.z += bias; v.w += bias;
        ((float4*)(g_xg1 + ((size_t)((blk * S_LEN + t0 + tloc) * GATES) + n0) * BST))[rest] = v;
    }
}

// ---------------- K2/K4: recurrent phases, batch-half pipelined, 7 rows/block ----
// Half A = local rows 0-3 (4), half B = local rows 4-6 (3).
// alpha: GEMM_A(t) + finalize_B(t-1). beta: GEMM_B(t) + finalize_A(t).
template<int PHASE>
__global__ void __launch_bounds__(NTH, 1) lstm_phase(
    const float* __restrict__ x,
    const float* __restrict__ wih0,
    const float* __restrict__ bih,
    const float* __restrict__ bhh,
    const float* __restrict__ fcw,
    const float* __restrict__ fcb,
    float* __restrict__ out)
{
    extern __shared__ float sm[];
    const float* Pg = (PHASE == 1) ? g_P1 : g_P2;

    const int tid = threadIdx.x;
    const int j   = tid & (HID - 1);
    const int kh  = tid >> 7;
    const int blk = blockIdx.x;
    const int bg0 = blk * RPB;
    const int valid = (BATCH - bg0 < RPB) ? (BATCH - bg0) : RPB;
    const int gb  = NSM + kh * 3;

    ulonglong2 wr[3][4];
    {
        const ulonglong2* PgD = (const ulonglong2*)Pg;
#pragma unroll
        for (int s = 0; s < 3; s++)
#pragma unroll
            for (int q = 0; q < 4; q++)
                wr[s][q] = __ldg(&PgD[(gb + s) * GATES + q * HID + j]);
    }

    float bias[4], wihr[4][DIN];
    if (PHASE == 1 && kh < 2) {
#pragma unroll
        for (int q = 0; q < 4; q++) {
            int r = q * HID + j;
            bias[q] = __ldg(bih + r) + __ldg(bhh + r);
#pragma unroll
            for (int d = 0; d < DIN; d++) wihr[q][d] = __ldg(wih0 + r * DIN + d);
        }
    }

    {
        const float4* src = (const float4*)Pg;
        float4*       dst = (float4*)(sm + OFF_WC);
        for (int i = tid; i < NSM * GATES; i += NTH) dst[i] = __ldg(src + i);
    }
    for (int i = tid; i < 1024; i += NTH) sm[OFF_HA + i] = 0.f;
    __syncthreads();

    const ulonglong2* WcD = (const ulonglong2*)(sm + OFF_WC);

    float c[2][2] = {{0.f, 0.f}, {0.f, 0.f}};
    float2 xqA[4], xqB[4];
    float  xvA[2][DIN], xvB[2][DIN];

    // -------- export helpers --------
    auto exportA = [&](float (&pr)[4][4], float (&prOwn)[4][2]) {
        float* XP = sm + OFF_XP;               // half A
        if (kh == 0) {
#pragma unroll
            for (int r = 2; r < 4; r++)
                *(float4*)(XP + r * 512 + j * 4) =
                    make_float4(pr[0][r], pr[1][r], pr[2][r], pr[3][r]);
#pragma unroll
            for (int q = 0; q < 4; q++) { prOwn[q][0] = pr[q][0]; prOwn[q][1] = pr[q][1]; }
        } else if (kh == 1) {
#pragma unroll
            for (int r = 0; r < 2; r++)
                *(float4*)(XP + r * 512 + j * 4) =
                    make_float4(pr[0][r], pr[1][r], pr[2][r], pr[3][r]);
#pragma unroll
            for (int q = 0; q < 4; q++) { prOwn[q][0] = pr[q][2]; prOwn[q][1] = pr[q][3]; }
        } else {
#pragma unroll
            for (int r = 0; r < 4; r++)
                *(float4*)(XP + 2048 + r * 512 + j * 4) =
                    make_float4(pr[0][r], pr[1][r], pr[2][r], pr[3][r]);
        }
    };
    auto exportB = [&](float (&pr)[4][3], float (&prOwn)[4][3]) {
        float* XP = sm + OFF_XP + 4096;        // half B
        if (kh == 0) {
            *(float4*)(XP + 2 * 512 + j * 4) =
                make_float4(pr[0][2], pr[1][2], pr[2][2], pr[3][2]);
#pragma unroll
            for (int q = 0; q < 4; q++) { prOwn[q][0] = pr[q][0]; prOwn[q][1] = pr[q][1]; }
        } else if (kh == 1) {
#pragma unroll
            for (int r = 0; r < 2; r++)
                *(float4*)(XP + r * 512 + j * 4) =
                    make_float4(pr[0][r], pr[1][r], pr[2][r], pr[3][r]);
#pragma unroll
            for (int q = 0; q < 4; q++) prOwn[q][0] = pr[q][2];
        } else {
#pragma unroll
            for (int r = 0; r < 3; r++)
                *(float4*)(XP + 2048 + r * 512 + j * 4) =
                    make_float4(pr[0][r], pr[1][r], pr[2][r], pr[3][r]);
        }
    };

    auto finalize_half = [&](int hoff, int half, int t, const float* prOwn0, const float* prOwn1,
                             float2 (&xq)[4], float (&xv)[2][DIN]) {
        const float* XP = sm + OFF_XP + half * 4096;
        const int nown = (kh == 0) ? 2 : (half == 0 ? 2 : 1);
#pragma unroll
        for (int r2 = 0; r2 < 2; r2++) {
            if (r2 >= nown) break;
            int rloc = 2 * kh + r2;
            const float* po = (r2 == 0) ? prOwn0 : prOwn1;
            float4 p0 = *(const float4*)(XP + rloc * 512 + j * 4);
            float4 p1 = *(const float4*)(XP + 2048 + rloc * 512 + j * 4);
            float gate[4];
            gate[0] = po[0] + p0.x + p1.x;
            gate[1] = po[1] + p0.y + p1.y;
            gate[2] = po[2] + p0.z + p1.z;
            gate[3] = po[3] + p0.w + p1.w;
            if (PHASE == 1) {
#pragma unroll
                for (int q = 0; q < 4; q++) {
                    float s = bias[q];
#pragma unroll
                    for (int d = 0; d < DIN; d++) s = fmaf(wihr[q][d], xv[r2][d], s);
                    gate[q] += s;
                }
            } else {
                gate[0] += (r2 == 0 ? xq[0].x : xq[0].y);
                gate[1] += (r2 == 0 ? xq[1].x : xq[1].y);
                gate[2] += (r2 == 0 ? xq[2].x : xq[2].y);
                gate[3] += (r2 == 0 ? xq[3].x : xq[3].y);
            }
            float cc = sigf(gate[1]) * c[half][r2] + sigf(gate[0]) * tanhf_fast(gate[2]);
            c[half][r2] = cc;
            float h = sigf(gate[3]) * tanhf_fast(cc);
            sm[hoff + rloc * HID + j] = h;
            if (PHASE == 1)
                g_h1[((size_t)(blk * S_LEN + t) * BST + half * 4 + rloc) * HID + j] =
                    __uint_as_float(f2tf32(h));   // pre-round for tensor-core gemm
        }
    };

    auto load_inputs = [&](int half, int t, float2 (&xq)[4], float (&xv)[2][DIN]) {
        if (kh >= 2) return;
        if (PHASE == 2) {
            const float* xp = g_xg1 + (size_t)(blk * S_LEN + t) * (GATES * BST);
            int off = half * 4 + 2 * kh;
#pragma unroll
            for (int q = 0; q < 4; q++)
                xq[q] = __ldg((const float2*)(xp + (q * HID + j) * BST + off));
        } else {
#pragma unroll
            for (int r2 = 0; r2 < 2; r2++) {
                int gr = bg0 + half * 4 + 2 * kh + r2;
                if (gr > BATCH - 1) gr = BATCH - 1;
                const float* xr = x + ((size_t)gr * S_LEN + t) * DIN;
#pragma unroll
                for (int d = 0; d < DIN; d++) xv[r2][d] = __ldg(xr + d);
            }
        }
    };

    float prOwnA[4][2];
    float prOwnBv[4][3];

    for (int t = 0; t < S_LEN; t++) {
        // ---- alpha: GEMM_A(t) + finalize_B(t-1) ----
        load_inputs(0, t, xqA, xvA);
        if (t > 0 && kh < 2) {
            float o0[4] = {prOwnBv[0][0], prOwnBv[1][0], prOwnBv[2][0], prOwnBv[3][0]};
            float o1[4] = {prOwnBv[0][1], prOwnBv[1][1], prOwnBv[2][1], prOwnBv[3][1]};
            finalize_half(OFF_HB, 1, t - 1, o0, o1, xqB, xvB);
        }
        {
            float prA[4][4];
            gemm_body<4>(kh, WcD, wr, gb, (const ulonglong2*)(sm + OFF_HA), j, prA);
            exportA(prA, prOwnA);
            __syncthreads();
            // ---- beta: GEMM_B(t) + finalize_A(t) ----
            load_inputs(1, t, xqB, xvB);
            if (kh < 2) {
                float o0[4] = {prOwnA[0][0], prOwnA[1][0], prOwnA[2][0], prOwnA[3][0]};
                float o1[4] = {prOwnA[0][1], prOwnA[1][1], prOwnA[2][1], prOwnA[3][1]};
                finalize_half(OFF_HA, 0, t, o0, o1, xqA, xvA);
            }
        }
        {
            float prBt[4][3];
            gemm_body<3>(kh, WcD, wr, gb, (const ulonglong2*)(sm + OFF_HB), j, prBt);
            exportB(prBt, prOwnBv);
        }
        __syncthreads();
    }
    // drain: finalize_B(511)
    if (kh < 2) {
        float o0[4] = {prOwnBv[0][0], prOwnBv[1][0], prOwnBv[2][0], prOwnBv[3][0]};
        float o1[4] = {prOwnBv[0][1], prOwnBv[1][1], prOwnBv[2][1], prOwnBv[3][1]};
        finalize_half(OFF_HB, 1, S_LEN - 1, o0, o1, xqB, xvB);
    }
    __syncthreads();

    if (PHASE == 2 && tid < 224) {
        int w = tid >> 5, lane = tid & 31;
        if (w < valid) {
            const float* hrow = sm + (w < 4 ? OFF_HA + w * HID : OFF_HB + (w - 4) * HID);
            float s = 0.f;
#pragma unroll
            for (int m = 0; m < HID; m += 32)
                s += hrow[lane + m] * __ldg(fcw + lane + m);
#pragma unroll
            for (int o = 16; o > 0; o >>= 1) s += __shfl_down_sync(0xffffffffu, s, o);
            if (lane == 0) out[bg0 + w] = s + __ldg(fcb);
        }
    }
}

// ---------------- launch ----------------
extern "C" void kernel_launch(void* const* d_in, const int* in_sizes, int n_in,
                              void* d_out, int out_size) {
    const float* x    = (const float*)d_in[0];
    const float* wih0 = (const float*)d_in[1];
    const float* whh0 = (const float*)d_in[2];
    const float* bih0 = (const float*)d_in[3];
    const float* bhh0 = (const float*)d_in[4];
    const float* wih1 = (const float*)d_in[5];
    const float* whh1 = (const float*)d_in[6];
    const float* bih1 = (const float*)d_in[7];
    const float* bhh1 = (const float*)d_in[8];
    const float* fcw  = (const float*)d_in[9];
    const float* fcb  = (const float*)d_in[10];
    float* out = (float*)d_out;
    (void)in_sizes; (void)n_in; (void)out_size;

    cudaFuncSetAttribute(lstm_phase<1>, cudaFuncAttributeMaxDynamicSharedMemorySize, PH_SMEM_BYTES);
    cudaFuncSetAttribute(lstm_phase<2>, cudaFuncAttributeMaxDynamicSharedMemorySize, PH_SMEM_BYTES);
    cudaFuncSetAttribute(xg1_mma,       cudaFuncAttributeMaxDynamicSharedMemorySize, TG_SMEM_BYTES);

    pack_kernel<<<(GATES * HID + 255) / 256, 256>>>(whh0, whh1);
    lstm_phase<1><<<NBLK, NTH, PH_SMEM_BYTES>>>(x, wih0, bih0, bhh0, fcw, fcb, out);
    xg1_mma<<<dim3(256, NBLK), TG_THREADS, TG_SMEM_BYTES>>>(wih1, bih1, bhh1);
    lstm_phase<2><<<NBLK, NTH, PH_SMEM_BYTES>>>(x, wih0, bih1, bhh1, fcw, fcb, out);
}

// round 15
// speedup vs baseline: 1.3911x; 1.1144x over previous
#include <cuda_runtime.h>

// ---------------- problem constants ----------------
#define S_LEN  512
#define DIN    5
#define HID    128
#define GATES  512
#define BATCH  1024
#define NBLK   147     // recurrence blocks: 146 x 7 rows + 1 x 2 rows
#define RPB    7       // rows per block (logical)
#define BST    8       // row stride in g_h1 / g_xg1 (padded)
#define NG     32      // k-groups (of 4) per 128-wide K
#define NSM    23      // k-groups cached in smem (rest in registers)
#define NTH    384     // phase threads = 128 j x 3 kh

// phase smem layout (float offsets)
#define OFF_WC  0
#define OFF_HA  (NSM*GATES*4)            // 47104 : hA [4][128]
#define OFF_HB  (OFF_HA + 512)           // 47616 : hB [3][128] (512 reserved)
#define OFF_XP  (OFF_HB + 512)           // 48128 : [2 half][2 slot][4 r][128 j][4 q]
#define PH_SMEM_BYTES ((OFF_XP + 8192)*4)   // 225280

// tf32 mma gemm smem: A[128][132] + B[64][132] + C[8192]
#define TG_THREADS 256
#define TG_PAD 132
#define TG_A_FLOATS (128*TG_PAD)         // 16896
#define TG_B_FLOATS (64*TG_PAD)          // 8448
#define TG_C_OFF    (TG_A_FLOATS + TG_B_FLOATS)   // 25344
#define TG_SMEM_BYTES ((TG_C_OFF + 8192)*4)       // 134144

// ---------------- global scratch (static) ----------------
__device__ __align__(16) float g_P1[NG * GATES * 4];   // packed w_hh0
__device__ __align__(16) float g_P2[NG * GATES * 4];   // packed w_hh1
__device__ __align__(16) float g_h1 [(size_t)NBLK * S_LEN * BST * HID];    // [blk][t][b8][j] (tf32-rounded)
__device__ __align__(16) float g_xg1[(size_t)NBLK * S_LEN * GATES * BST];  // [blk][t][col][b8]

// ---------------- helpers ----------------
typedef unsigned long long u64;
__device__ __forceinline__ void ffma2(u64 &d, u64 a, u64 b) {
    asm("fma.rn.f32x2 %0, %1, %2, %0;" : "+l"(d) : "l"(a), "l"(b));
}
__device__ __forceinline__ float flo(u64 v) { return __uint_as_float((unsigned)v); }
__device__ __forceinline__ float fhi(u64 v) { return __uint_as_float((unsigned)(v >> 32)); }
__device__ __forceinline__ float sigf(float x) {
    return __fdividef(1.0f, 1.0f + __expf(-x));
}
__device__ __forceinline__ float tanhf_fast(float x) {
    float e = __expf(2.0f * x);
    return 1.0f - __fdividef(2.0f, e + 1.0f);
}
__device__ __forceinline__ unsigned f2tf32(float f) {
    unsigned r;
    asm("cvt.rna.tf32.f32 %0, %1;" : "=r"(r) : "f"(f));
    return r;
}
__device__ __forceinline__ void mma_tf32(float (&d)[4], const unsigned (&a)[4],
                                         const unsigned (&b)[2]) {
    asm("mma.sync.aligned.m16n8k8.row.col.f32.tf32.tf32.f32 "
        "{%0,%1,%2,%3}, {%4,%5,%6,%7}, {%8,%9}, {%0,%1,%2,%3};"
        : "+f"(d[0]), "+f"(d[1]), "+f"(d[2]), "+f"(d[3])
        : "r"(a[0]), "r"(a[1]), "r"(a[2]), "r"(a[3]), "r"(b[0]), "r"(b[1]));
}

// smem-group accumulation over NB batch rows (phase kernels)
template<int G0, int G1, int NB>
__device__ __forceinline__ void accum_smem(u64 (&acc)[4][NB],
                                           const ulonglong2* __restrict__ W,
                                           const ulonglong2* __restrict__ H,
                                           int j) {
#pragma unroll
    for (int g = G0; g < G1; g++) {
        ulonglong2 w[4];
#pragma unroll
        for (int q = 0; q < 4; q++) w[q] = W[g * GATES + q * HID + j];
#pragma unroll
        for (int b = 0; b < NB; b++) {
            ulonglong2 hv = H[b * 32 + g];
#pragma unroll
            for (int q = 0; q < 4; q++) {
                ffma2(acc[q][b], w[q].x, hv.x);
                ffma2(acc[q][b], w[q].y, hv.y);
            }
        }
    }
}

template<int NB>
__device__ __forceinline__ void gemm_body(int kh, const ulonglong2* __restrict__ WcD,
                                          const ulonglong2 (&wr)[3][4], int gb,
                                          const ulonglong2* __restrict__ H, int j,
                                          float (&pr)[4][NB]) {
    u64 acc[4][NB];
#pragma unroll
    for (int q = 0; q < 4; q++)
#pragma unroll
        for (int b = 0; b < NB; b++) acc[q][b] = 0ull;
    if (kh == 0)      accum_smem<0,  7,  NB>(acc, WcD, H, j);
    else if (kh == 1) accum_smem<7,  14, NB>(acc, WcD, H, j);
    else              accum_smem<14, NSM, NB>(acc, WcD, H, j);
#pragma unroll
    for (int s = 0; s < 3; s++) {
#pragma unroll
        for (int b = 0; b < NB; b++) {
            ulonglong2 hv = H[b * 32 + gb + s];
#pragma unroll
            for (int q = 0; q < 4; q++) {
                ffma2(acc[q][b], wr[s][q].x, hv.x);
                ffma2(acc[q][b], wr[s][q].y, hv.y);
            }
        }
    }
#pragma unroll
    for (int q = 0; q < 4; q++)
#pragma unroll
        for (int b = 0; b < NB; b++) pr[q][b] = flo(acc[q][b]) + fhi(acc[q][b]);
}

// ---------------- K1: pack weights (recurrence only) ----------------
__global__ void pack_kernel(const float* __restrict__ whh0,
                            const float* __restrict__ whh1) {
    int i = blockIdx.x * blockDim.x + threadIdx.x;
    if (i >= GATES * HID) return;
    int col = i / HID, k = i % HID;
    int g = k >> 2, dk = k & 3;
    size_t o = ((size_t)g * GATES + col) * 4 + dk;
    g_P1[o] = whh0[col * HID + k];
    g_P2[o] = whh1[col * HID + k];
}

// ---------------- K3: xg1 = h1 @ w_ih1^T + biases  (tf32 tensor-core) ----------------
// grid (32 mt, NBLK). CTA: M=128 (16 t x 8 b), K=128, loops all 8 N-slices of 64.
// A staged ONCE; B slices register-prefetched one ahead. 8 warps, warp tile 32x32.
__global__ void __launch_bounds__(TG_THREADS, 1) xg1_mma(
    const float* __restrict__ wih1,
    const float* __restrict__ bih1,
    const float* __restrict__ bhh1)
{
    extern __shared__ float smf[];
    unsigned* As = (unsigned*)smf;                  // [128][132] tf32 (rows = m, cols = k)
    unsigned* Bs = (unsigned*)(smf + TG_A_FLOATS);  // [64][132]  tf32 (rows = n, cols = k)
    float*    Cs = smf + TG_C_OFF;                  // [16 t][64 n][8 b]

    const int tid  = threadIdx.x;
    const int lane = tid & 31;
    const int wid  = tid >> 5;         // 0..7
    const int wm   = wid >> 1;         // 0..3 -> m offset 32*wm
    const int wn   = wid & 1;          // 0..1 -> n offset 32*wn
    const int mt   = blockIdx.x;
    const int blk  = blockIdx.y;
    const int t0   = mt * 16;

    // B slice prefetch: 2048 float4 per slice, 8 per thread (coalesced i = tid + 256k)
    float4 bpre[8];
    auto loadB = [&](int nt) {
        const float4* Bg = (const float4*)(wih1 + (size_t)nt * 64 * HID);
#pragma unroll
        for (int k = 0; k < 8; k++) bpre[k] = __ldg(Bg + tid + 256 * k);
    };
    auto stsB = [&]() {
#pragma unroll
        for (int k = 0; k < 8; k++) {
            int i = tid + 256 * k;
            int row = i >> 5, c4 = i & 31;
            unsigned* bd = Bs + row * TG_PAD + c4 * 4;
            bd[0] = f2tf32(bpre[k].x); bd[1] = f2tf32(bpre[k].y);
            bd[2] = f2tf32(bpre[k].z); bd[3] = f2tf32(bpre[k].w);
        }
    };

    // stage A once (h1 already tf32-rounded: pure copy), prefetch B0
    loadB(0);
    {
        const float4* Ag = (const float4*)(g_h1 + (size_t)(blk * S_LEN + t0) * (BST * HID));
        for (int i = tid; i < 128 * 32; i += TG_THREADS) {   // 32 float4 per row
            int row = i >> 5, c4 = i & 31;
            float4 av = __ldg(Ag + i);
            *(float4*)((float*)As + row * TG_PAD + c4 * 4) = av;
        }
    }
    stsB();
    __syncthreads();

    const int g   = lane >> 2;   // 0..7
    const int tig = lane & 3;    // 0..3

    for (int nt = 0; nt < 8; nt++) {
        const int n0 = nt * 64;
        if (nt + 1 < 8) loadB(nt + 1);   // LDG issued before mma: latency hidden

        float acc[2][4][4];
#pragma unroll
        for (int ms = 0; ms < 2; ms++)
#pragma unroll
            for (int ns = 0; ns < 4; ns++)
#pragma unroll
                for (int e = 0; e < 4; e++) acc[ms][ns][e] = 0.f;

#pragma unroll 2
        for (int ks = 0; ks < 16; ks++) {
            const int k0 = ks * 8;
            unsigned a[2][4], b[4][2];
#pragma unroll
            for (int ms = 0; ms < 2; ms++) {
                int r0 = wm * 32 + ms * 16 + g;
                a[ms][0] = As[r0 * TG_PAD + k0 + tig];
                a[ms][1] = As[(r0 + 8) * TG_PAD + k0 + tig];
                a[ms][2] = As[r0 * TG_PAD + k0 + tig + 4];
                a[ms][3] = As[(r0 + 8) * TG_PAD + k0 + tig + 4];
            }
#pragma unroll
            for (int ns = 0; ns < 4; ns++) {
                int nb = wn * 32 + ns * 8 + g;
                b[ns][0] = Bs[nb * TG_PAD + k0 + tig];
                b[ns][1] = Bs[nb * TG_PAD + k0 + tig + 4];
            }
#pragma unroll
            for (int ms = 0; ms < 2; ms++)
#pragma unroll
                for (int ns = 0; ns < 4; ns++)
                    mma_tf32(acc[ms][ns], a[ms], b[ns]);
        }
        __syncthreads();   // mma done reading Bs; prior C store done (program order)

        // C-stage: [tloc(16)][n(64)][b(8)]
#pragma unroll
        for (int ms = 0; ms < 2; ms++) {
#pragma unroll
            for (int ns = 0; ns < 4; ns++) {
                int r0 = wm * 32 + ms * 16 + g;
                int r2 = r0 + 8;
                int c0 = wn * 32 + ns * 8 + 2 * tig;
                Cs[(r0 >> 3) * 512 + c0 * 8 + (r0 & 7)]       = acc[ms][ns][0];
                Cs[(r0 >> 3) * 512 + (c0 + 1) * 8 + (r0 & 7)] = acc[ms][ns][1];
                Cs[(r2 >> 3) * 512 + c0 * 8 + (r2 & 7)]       = acc[ms][ns][2];
                Cs[(r2 >> 3) * 512 + (c0 + 1) * 8 + (r2 & 7)] = acc[ms][ns][3];
            }
        }
        if (nt + 1 < 8) stsB();          // publish next B slice
        __syncthreads();

        // coalesced store with bias: 2048 float4, [t][n][b] matches g_xg1 [col][b8]
        for (int i = tid; i < 2048; i += TG_THREADS) {
            int tloc = i >> 7;          // 128 float4 per t
            int rest = i & 127;         // n*2 + (b>>2)
            int n = rest >> 1;
            float4 v = ((const float4*)Cs)[i];
            float bias = __ldg(bih1 + n0 + n) + __ldg(bhh1 + n0 + n);
            v.x += bias; v.y += bias; v.z += bias; v.w += bias;
            ((float4*)(g_xg1 + ((size_t)((blk * S_LEN + t0 + tloc) * GATES) + n0) * BST))[rest] = v;
        }
    }
}

// ---------------- K2/K4: recurrent phases, batch-half pipelined, 7 rows/block ----
// Half A = local rows 0-3 (4), half B = local rows 4-6 (3).
// alpha: GEMM_A(t) + finalize_B(t-1). beta: GEMM_B(t) + finalize_A(t).
template<int PHASE>
__global__ void __launch_bounds__(NTH, 1) lstm_phase(
    const float* __restrict__ x,
    const float* __restrict__ wih0,
    const float* __restrict__ bih,
    const float* __restrict__ bhh,
    const float* __restrict__ fcw,
    const float* __restrict__ fcb,
    float* __restrict__ out)
{
    extern __shared__ float sm[];
    const float* Pg = (PHASE == 1) ? g_P1 : g_P2;

    const int tid = threadIdx.x;
    const int j   = tid & (HID - 1);
    const int kh  = tid >> 7;
    const int blk = blockIdx.x;
    const int bg0 = blk * RPB;
    const int valid = (BATCH - bg0 < RPB) ? (BATCH - bg0) : RPB;
    const int gb  = NSM + kh * 3;

    ulonglong2 wr[3][4];
    {
        const ulonglong2* PgD = (const ulonglong2*)Pg;
#pragma unroll
        for (int s = 0; s < 3; s++)
#pragma unroll
            for (int q = 0; q < 4; q++)
                wr[s][q] = __ldg(&PgD[(gb + s) * GATES + q * HID + j]);
    }

    float bias[4], wihr[4][DIN];
    if (PHASE == 1 && kh < 2) {
#pragma unroll
        for (int q = 0; q < 4; q++) {
            int r = q * HID + j;
            bias[q] = __ldg(bih + r) + __ldg(bhh + r);
#pragma unroll
            for (int d = 0; d < DIN; d++) wihr[q][d] = __ldg(wih0 + r * DIN + d);
        }
    }

    {
        const float4* src = (const float4*)Pg;
        float4*       dst = (float4*)(sm + OFF_WC);
        for (int i = tid; i < NSM * GATES; i += NTH) dst[i] = __ldg(src + i);
    }
    for (int i = tid; i < 1024; i += NTH) sm[OFF_HA + i] = 0.f;
    __syncthreads();

    const ulonglong2* WcD = (const ulonglong2*)(sm + OFF_WC);

    float c[2][2] = {{0.f, 0.f}, {0.f, 0.f}};
    float2 xqA[4], xqB[4];
    float  xvA[2][DIN], xvB[2][DIN];

    // -------- export helpers --------
    auto exportA = [&](float (&pr)[4][4], float (&prOwn)[4][2]) {
        float* XP = sm + OFF_XP;               // half A
        if (kh == 0) {
#pragma unroll
            for (int r = 2; r < 4; r++)
                *(float4*)(XP + r * 512 + j * 4) =
                    make_float4(pr[0][r], pr[1][r], pr[2][r], pr[3][r]);
#pragma unroll
            for (int q = 0; q < 4; q++) { prOwn[q][0] = pr[q][0]; prOwn[q][1] = pr[q][1]; }
        } else if (kh == 1) {
#pragma unroll
            for (int r = 0; r < 2; r++)
                *(float4*)(XP + r * 512 + j * 4) =
                    make_float4(pr[0][r], pr[1][r], pr[2][r], pr[3][r]);
#pragma unroll
            for (int q = 0; q < 4; q++) { prOwn[q][0] = pr[q][2]; prOwn[q][1] = pr[q][3]; }
        } else {
#pragma unroll
            for (int r = 0; r < 4; r++)
                *(float4*)(XP + 2048 + r * 512 + j * 4) =
                    make_float4(pr[0][r], pr[1][r], pr[2][r], pr[3][r]);
        }
    };
    auto exportB = [&](float (&pr)[4][3], float (&prOwn)[4][3]) {
        float* XP = sm + OFF_XP + 4096;        // half B
        if (kh == 0) {
            *(float4*)(XP + 2 * 512 + j * 4) =
                make_float4(pr[0][2], pr[1][2], pr[2][2], pr[3][2]);
#pragma unroll
            for (int q = 0; q < 4; q++) { prOwn[q][0] = pr[q][0]; prOwn[q][1] = pr[q][1]; }
        } else if (kh == 1) {
#pragma unroll
            for (int r = 0; r < 2; r++)
                *(float4*)(XP + r * 512 + j * 4) =
                    make_float4(pr[0][r], pr[1][r], pr[2][r], pr[3][r]);
#pragma unroll
            for (int q = 0; q < 4; q++) prOwn[q][0] = pr[q][2];
        } else {
#pragma unroll
            for (int r = 0; r < 3; r++)
                *(float4*)(XP + 2048 + r * 512 + j * 4) =
                    make_float4(pr[0][r], pr[1][r], pr[2][r], pr[3][r]);
        }
    };

    auto finalize_half = [&](int hoff, int half, int t, const float* prOwn0, const float* prOwn1,
                             float2 (&xq)[4], float (&xv)[2][DIN]) {
        const float* XP = sm + OFF_XP + half * 4096;
        const int nown = (kh == 0) ? 2 : (half == 0 ? 2 : 1);
#pragma unroll
        for (int r2 = 0; r2 < 2; r2++) {
            if (r2 >= nown) break;
            int rloc = 2 * kh + r2;
            const float* po = (r2 == 0) ? prOwn0 : prOwn1;
            float4 p0 = *(const float4*)(XP + rloc * 512 + j * 4);
            float4 p1 = *(const float4*)(XP + 2048 + rloc * 512 + j * 4);
            float gate[4];
            gate[0] = po[0] + p0.x + p1.x;
            gate[1] = po[1] + p0.y + p1.y;
            gate[2] = po[2] + p0.z + p1.z;
            gate[3] = po[3] + p0.w + p1.w;
            if (PHASE == 1) {
#pragma unroll
                for (int q = 0; q < 4; q++) {
                    float s = bias[q];
#pragma unroll
                    for (int d = 0; d < DIN; d++) s = fmaf(wihr[q][d], xv[r2][d], s);
                    gate[q] += s;
                }
            } else {
                gate[0] += (r2 == 0 ? xq[0].x : xq[0].y);
                gate[1] += (r2 == 0 ? xq[1].x : xq[1].y);
                gate[2] += (r2 == 0 ? xq[2].x : xq[2].y);
                gate[3] += (r2 == 0 ? xq[3].x : xq[3].y);
            }
            float cc = sigf(gate[1]) * c[half][r2] + sigf(gate[0]) * tanhf_fast(gate[2]);
            c[half][r2] = cc;
            float h = sigf(gate[3]) * tanhf_fast(cc);
            sm[hoff + rloc * HID + j] = h;
            if (PHASE == 1)
                g_h1[((size_t)(blk * S_LEN + t) * BST + half * 4 + rloc) * HID + j] =
                    __uint_as_float(f2tf32(h));   // pre-round for tensor-core gemm
        }
    };

    auto load_inputs = [&](int half, int t, float2 (&xq)[4], float (&xv)[2][DIN]) {
        if (kh >= 2) return;
        if (PHASE == 2) {
            const float* xp = g_xg1 + (size_t)(blk * S_LEN + t) * (GATES * BST);
            int off = half * 4 + 2 * kh;
#pragma unroll
            for (int q = 0; q < 4; q++)
                xq[q] = __ldg((const float2*)(xp + (q * HID + j) * BST + off));
        } else {
#pragma unroll
            for (int r2 = 0; r2 < 2; r2++) {
                int gr = bg0 + half * 4 + 2 * kh + r2;
                if (gr > BATCH - 1) gr = BATCH - 1;
                const float* xr = x + ((size_t)gr * S_LEN + t) * DIN;
#pragma unroll
                for (int d = 0; d < DIN; d++) xv[r2][d] = __ldg(xr + d);
            }
        }
    };

    float prOwnA[4][2];
    float prOwnBv[4][3];

    for (int t = 0; t < S_LEN; t++) {
        // ---- alpha: GEMM_A(t) + finalize_B(t-1) ----
        load_inputs(0, t, xqA, xvA);
        if (t > 0 && kh < 2) {
            float o0[4] = {prOwnBv[0][0], prOwnBv[1][0], prOwnBv[2][0], prOwnBv[3][0]};
            float o1[4] = {prOwnBv[0][1], prOwnBv[1][1], prOwnBv[2][1], prOwnBv[3][1]};
            finalize_half(OFF_HB, 1, t - 1, o0, o1, xqB, xvB);
        }
        {
            float prA[4][4];
            gemm_body<4>(kh, WcD, wr, gb, (const ulonglong2*)(sm + OFF_HA), j, prA);
            exportA(prA, prOwnA);
            __syncthreads();
            // ---- beta: GEMM_B(t) + finalize_A(t) ----
            load_inputs(1, t, xqB, xvB);
            if (kh < 2) {
                float o0[4] = {prOwnA[0][0], prOwnA[1][0], prOwnA[2][0], prOwnA[3][0]};
                float o1[4] = {prOwnA[0][1], prOwnA[1][1], prOwnA[2][1], prOwnA[3][1]};
                finalize_half(OFF_HA, 0, t, o0, o1, xqA, xvA);
            }
        }
        {
            float prBt[4][3];
            gemm_body<3>(kh, WcD, wr, gb, (const ulonglong2*)(sm + OFF_HB), j, prBt);
            exportB(prBt, prOwnBv);
        }
        __syncthreads();
    }
    // drain: finalize_B(511)
    if (kh < 2) {
        float o0[4] = {prOwnBv[0][0], prOwnBv[1][0], prOwnBv[2][0], prOwnBv[3][0]};
        float o1[4] = {prOwnBv[0][1], prOwnBv[1][1], prOwnBv[2][1], prOwnBv[3][1]};
        finalize_half(OFF_HB, 1, S_LEN - 1, o0, o1, xqB, xvB);
    }
    __syncthreads();

    if (PHASE == 2 && tid < 224) {
        int w = tid >> 5, lane = tid & 31;
        if (w < valid) {
            const float* hrow = sm + (w < 4 ? OFF_HA + w * HID : OFF_HB + (w - 4) * HID);
            float s = 0.f;
#pragma unroll
            for (int m = 0; m < HID; m += 32)
                s += hrow[lane + m] * __ldg(fcw + lane + m);
#pragma unroll
            for (int o = 16; o > 0; o >>= 1) s += __shfl_down_sync(0xffffffffu, s, o);
            if (lane == 0) out[bg0 + w] = s + __ldg(fcb);
        }
    }
}

// ---------------- launch ----------------
extern "C" void kernel_launch(void* const* d_in, const int* in_sizes, int n_in,
                              void* d_out, int out_size) {
    const float* x    = (const float*)d_in[0];
    const float* wih0 = (const float*)d_in[1];
    const float* whh0 = (const float*)d_in[2];
    const float* bih0 = (const float*)d_in[3];
    const float* bhh0 = (const float*)d_in[4];
    const float* wih1 = (const float*)d_in[5];
    const float* whh1 = (const float*)d_in[6];
    const float* bih1 = (const float*)d_in[7];
    const float* bhh1 = (const float*)d_in[8];
    const float* fcw  = (const float*)d_in[9];
    const float* fcb  = (const float*)d_in[10];
    float* out = (float*)d_out;
    (void)in_sizes; (void)n_in; (void)out_size;

    cudaFuncSetAttribute(lstm_phase<1>, cudaFuncAttributeMaxDynamicSharedMemorySize, PH_SMEM_BYTES);
    cudaFuncSetAttribute(lstm_phase<2>, cudaFuncAttributeMaxDynamicSharedMemorySize, PH_SMEM_BYTES);
    cudaFuncSetAttribute(xg1_mma,       cudaFuncAttributeMaxDynamicSharedMemorySize, TG_SMEM_BYTES);

    pack_kernel<<<(GATES * HID + 255) / 256, 256>>>(whh0, whh1);
    lstm_phase<1><<<NBLK, NTH, PH_SMEM_BYTES>>>(x, wih0, bih0, bhh0, fcw, fcb, out);
    xg1_mma<<<dim3(32, NBLK), TG_THREADS, TG_SMEM_BYTES>>>(wih1, bih1, bhh1);
    lstm_phase<2><<<NBLK, NTH, PH_SMEM_BYTES>>>(x, wih0, bih1, bhh1, fcw, fcb, out);
}

// round 16
// speedup vs baseline: 1.4205x; 1.0212x over previous
#include <cuda_runtime.h>

// ---------------- problem constants ----------------
#define S_LEN  512
#define DIN    5
#define HID    128
#define GATES  512
#define BATCH  1024
#define NBLK   147     // recurrence blocks: 146 x 7 rows + 1 x 2 rows
#define RPB    7       // rows per block (logical)
#define BST    8       // row stride in g_h1 / g_xg1 (padded)
#define NG     32      // k-groups (of 4) per 128-wide K
#define NSM    23      // k-groups cached in smem (rest in registers)
#define NTH    384     // phase threads = 128 j x 3 kh

// phase smem layout (float offsets)
#define OFF_WC  0
#define OFF_HA  (NSM*GATES*4)            // 47104 : hA [4][128]
#define OFF_HB  (OFF_HA + 512)           // 47616 : hB [3][128] (512 reserved)
#define OFF_XP  (OFF_HB + 512)           // 48128 : [2 half][2 slot][4 r][128 j][4 q]
#define PH_SMEM_BYTES ((OFF_XP + 8192)*4)   // 225280

// tf32 mma gemm smem: A[64][132] + B[64][132] + C[4096]  -> 2 CTAs/SM
#define TG_THREADS 256
#define TG_PAD 132
#define TG_A_FLOATS (64*TG_PAD)          // 8448
#define TG_B_FLOATS (64*TG_PAD)          // 8448
#define TG_C_OFF    (TG_A_FLOATS + TG_B_FLOATS)   // 16896
#define TG_SMEM_BYTES ((TG_C_OFF + 4096)*4)       // 83968

// ---------------- global scratch (static) ----------------
__device__ __align__(16) float g_P1[NG * GATES * 4];   // packed w_hh0
__device__ __align__(16) float g_P2[NG * GATES * 4];   // packed w_hh1
__device__ __align__(16) float g_h1 [(size_t)NBLK * S_LEN * BST * HID];    // [blk][t][b8][j] (tf32-rounded)
__device__ __align__(16) float g_xg1[(size_t)NBLK * S_LEN * GATES * BST];  // [blk][t][col][b8]

// ---------------- helpers ----------------
typedef unsigned long long u64;
__device__ __forceinline__ void ffma2(u64 &d, u64 a, u64 b) {
    asm("fma.rn.f32x2 %0, %1, %2, %0;" : "+l"(d) : "l"(a), "l"(b));
}
__device__ __forceinline__ float flo(u64 v) { return __uint_as_float((unsigned)v); }
__device__ __forceinline__ float fhi(u64 v) { return __uint_as_float((unsigned)(v >> 32)); }
__device__ __forceinline__ float sigf(float x) {
    return __fdividef(1.0f, 1.0f + __expf(-x));
}
__device__ __forceinline__ float tanhf_fast(float x) {
    float e = __expf(2.0f * x);
    return 1.0f - __fdividef(2.0f, e + 1.0f);
}
__device__ __forceinline__ unsigned f2tf32(float f) {
    unsigned r;
    asm("cvt.rna.tf32.f32 %0, %1;" : "=r"(r) : "f"(f));
    return r;
}
__device__ __forceinline__ void mma_tf32(float (&d)[4], const unsigned (&a)[4],
                                         const unsigned (&b)[2]) {
    asm("mma.sync.aligned.m16n8k8.row.col.f32.tf32.tf32.f32 "
        "{%0,%1,%2,%3}, {%4,%5,%6,%7}, {%8,%9}, {%0,%1,%2,%3};"
        : "+f"(d[0]), "+f"(d[1]), "+f"(d[2]), "+f"(d[3])
        : "r"(a[0]), "r"(a[1]), "r"(a[2]), "r"(a[3]), "r"(b[0]), "r"(b[1]));
}

// smem-group accumulation over NB batch rows (phase kernels)
template<int G0, int G1, int NB>
__device__ __forceinline__ void accum_smem(u64 (&acc)[4][NB],
                                           const ulonglong2* __restrict__ W,
                                           const ulonglong2* __restrict__ H,
                                           int j) {
#pragma unroll
    for (int g = G0; g < G1; g++) {
        ulonglong2 w[4];
#pragma unroll
        for (int q = 0; q < 4; q++) w[q] = W[g * GATES + q * HID + j];
#pragma unroll
        for (int b = 0; b < NB; b++) {
            ulonglong2 hv = H[b * 32 + g];
#pragma unroll
            for (int q = 0; q < 4; q++) {
                ffma2(acc[q][b], w[q].x, hv.x);
                ffma2(acc[q][b], w[q].y, hv.y);
            }
        }
    }
}

template<int NB>
__device__ __forceinline__ void gemm_body(int kh, const ulonglong2* __restrict__ WcD,
                                          const ulonglong2 (&wr)[3][4], int gb,
                                          const ulonglong2* __restrict__ H, int j,
                                          float (&pr)[4][NB]) {
    u64 acc[4][NB];
#pragma unroll
    for (int q = 0; q < 4; q++)
#pragma unroll
        for (int b = 0; b < NB; b++) acc[q][b] = 0ull;
    if (kh == 0)      accum_smem<0,  7,  NB>(acc, WcD, H, j);
    else if (kh == 1) accum_smem<7,  14, NB>(acc, WcD, H, j);
    else              accum_smem<14, NSM, NB>(acc, WcD, H, j);
#pragma unroll
    for (int s = 0; s < 3; s++) {
#pragma unroll
        for (int b = 0; b < NB; b++) {
            ulonglong2 hv = H[b * 32 + gb + s];
#pragma unroll
            for (int q = 0; q < 4; q++) {
                ffma2(acc[q][b], wr[s][q].x, hv.x);
                ffma2(acc[q][b], wr[s][q].y, hv.y);
            }
        }
    }
#pragma unroll
    for (int q = 0; q < 4; q++)
#pragma unroll
        for (int b = 0; b < NB; b++) pr[q][b] = flo(acc[q][b]) + fhi(acc[q][b]);
}

// ---------------- K1: pack weights (recurrence only) ----------------
__global__ void pack_kernel(const float* __restrict__ whh0,
                            const float* __restrict__ whh1) {
    int i = blockIdx.x * blockDim.x + threadIdx.x;
    if (i >= GATES * HID) return;
    int col = i / HID, k = i % HID;
    int g = k >> 2, dk = k & 3;
    size_t o = ((size_t)g * GATES + col) * 4 + dk;
    g_P1[o] = whh0[col * HID + k];
    g_P2[o] = whh1[col * HID + k];
}

// ---------------- K3: xg1 = h1 @ w_ih1^T + biases  (tf32 tensor-core) ----------------
// grid (64 mt, NBLK), 2 CTAs/SM. CTA: M=64 (8 t x 8 b), K=128, loops 8 N-slices of 64.
// A staged ONCE per CTA; B slices register-prefetched one ahead.
// 8 warps in 4m x 2n grid; warp tile 16x32 via m16n8k8 (1 msub x 4 nsub).
__global__ void __launch_bounds__(TG_THREADS, 2) xg1_mma(
    const float* __restrict__ wih1,
    const float* __restrict__ bih1,
    const float* __restrict__ bhh1)
{
    extern __shared__ float smf[];
    unsigned* As = (unsigned*)smf;                  // [64][132] tf32 (rows = m, cols = k)
    unsigned* Bs = (unsigned*)(smf + TG_A_FLOATS);  // [64][132] tf32 (rows = n, cols = k)
    float*    Cs = smf + TG_C_OFF;                  // [8 t][64 n][8 b]

    const int tid  = threadIdx.x;
    const int lane = tid & 31;
    const int wid  = tid >> 5;         // 0..7
    const int wm   = wid >> 1;         // 0..3 -> m offset 16*wm
    const int wn   = wid & 1;          // 0..1 -> n offset 32*wn
    const int mt   = blockIdx.x;       // 0..63
    const int blk  = blockIdx.y;
    const int t0   = mt * 8;

    // B slice prefetch: 2048 float4 per slice, 8 per thread (coalesced)
    float4 bpre[8];
    auto loadB = [&](int nt) {
        const float4* Bg = (const float4*)(wih1 + (size_t)nt * 64 * HID);
#pragma unroll
        for (int k = 0; k < 8; k++) bpre[k] = __ldg(Bg + tid + 256 * k);
    };
    auto stsB = [&]() {
#pragma unroll
        for (int k = 0; k < 8; k++) {
            int i = tid + 256 * k;
            int row = i >> 5, c4 = i & 31;
            unsigned* bd = Bs + row * TG_PAD + c4 * 4;
            bd[0] = f2tf32(bpre[k].x); bd[1] = f2tf32(bpre[k].y);
            bd[2] = f2tf32(bpre[k].z); bd[3] = f2tf32(bpre[k].w);
        }
    };

    // stage A once (h1 already tf32-rounded: pure copy), prefetch B0
    loadB(0);
    {
        const float4* Ag = (const float4*)(g_h1 + (size_t)(blk * S_LEN + t0) * (BST * HID));
#pragma unroll
        for (int k = 0; k < 8; k++) {
            int i = tid + 256 * k;        // 2048 float4 = 64 rows x 32
            int row = i >> 5, c4 = i & 31;
            float4 av = __ldg(Ag + i);
            *(float4*)((float*)As + row * TG_PAD + c4 * 4) = av;
        }
    }
    stsB();
    __syncthreads();

    const int g   = lane >> 2;   // 0..7
    const int tig = lane & 3;    // 0..3

    for (int nt = 0; nt < 8; nt++) {
        const int n0 = nt * 64;
        if (nt + 1 < 8) loadB(nt + 1);   // LDG issued before mma: latency hidden

        float acc[4][4];
#pragma unroll
        for (int ns = 0; ns < 4; ns++)
#pragma unroll
            for (int e = 0; e < 4; e++) acc[ns][e] = 0.f;

#pragma unroll 2
        for (int ks = 0; ks < 16; ks++) {
            const int k0 = ks * 8;
            unsigned a[4], b[4][2];
            int r0 = wm * 16 + g;
            a[0] = As[r0 * TG_PAD + k0 + tig];
            a[1] = As[(r0 + 8) * TG_PAD + k0 + tig];
            a[2] = As[r0 * TG_PAD + k0 + tig + 4];
            a[3] = As[(r0 + 8) * TG_PAD + k0 + tig + 4];
#pragma unroll
            for (int ns = 0; ns < 4; ns++) {
                int nb = wn * 32 + ns * 8 + g;
                b[ns][0] = Bs[nb * TG_PAD + k0 + tig];
                b[ns][1] = Bs[nb * TG_PAD + k0 + tig + 4];
            }
#pragma unroll
            for (int ns = 0; ns < 4; ns++)
                mma_tf32(acc[ns], a, b[ns]);
        }
        __syncthreads();   // mma done reading Bs; prior C store done (program order)

        // C-stage: [tloc(8)][n(64)][b(8)]
#pragma unroll
        for (int ns = 0; ns < 4; ns++) {
            int r0 = wm * 16 + g;
            int r2 = r0 + 8;
            int c0 = wn * 32 + ns * 8 + 2 * tig;
            Cs[(r0 >> 3) * 512 + c0 * 8 + (r0 & 7)]       = acc[ns][0];
            Cs[(r0 >> 3) * 512 + (c0 + 1) * 8 + (r0 & 7)] = acc[ns][1];
            Cs[(r2 >> 3) * 512 + c0 * 8 + (r2 & 7)]       = acc[ns][2];
            Cs[(r2 >> 3) * 512 + (c0 + 1) * 8 + (r2 & 7)] = acc[ns][3];
        }
        if (nt + 1 < 8) stsB();          // publish next B slice
        __syncthreads();

        // coalesced store with bias: 1024 float4, [t][n][b] matches g_xg1 [col][b8]
        for (int i = tid; i < 1024; i += TG_THREADS) {
            int tloc = i >> 7;          // 128 float4 per t
            int rest = i & 127;         // n*2 + (b>>2)
            int n = rest >> 1;
            float4 v = ((const float4*)Cs)[i];
            float bias = __ldg(bih1 + n0 + n) + __ldg(bhh1 + n0 + n);
            v.x += bias; v.y += bias; v.z += bias; v.w += bias;
            ((float4*)(g_xg1 + ((size_t)((blk * S_LEN + t0 + tloc) * GATES) + n0) * BST))[rest] = v;
        }
    }
}

// ---------------- K2/K4: recurrent phases, batch-half pipelined, 7 rows/block ----
// Half A = local rows 0-3 (4), half B = local rows 4-6 (3).
// alpha: GEMM_A(t) + finalize_B(t-1). beta: GEMM_B(t) + finalize_A(t).
template<int PHASE>
__global__ void __launch_bounds__(NTH, 1) lstm_phase(
    const float* __restrict__ x,
    const float* __restrict__ wih0,
    const float* __restrict__ bih,
    const float* __restrict__ bhh,
    const float* __restrict__ fcw,
    const float* __restrict__ fcb,
    float* __restrict__ out)
{
    extern __shared__ float sm[];
    const float* Pg = (PHASE == 1) ? g_P1 : g_P2;

    const int tid = threadIdx.x;
    const int j   = tid & (HID - 1);
    const int kh  = tid >> 7;
    const int blk = blockIdx.x;
    const int bg0 = blk * RPB;
    const int valid = (BATCH - bg0 < RPB) ? (BATCH - bg0) : RPB;
    const int gb  = NSM + kh * 3;

    ulonglong2 wr[3][4];
    {
        const ulonglong2* PgD = (const ulonglong2*)Pg;
#pragma unroll
        for (int s = 0; s < 3; s++)
#pragma unroll
            for (int q = 0; q < 4; q++)
                wr[s][q] = __ldg(&PgD[(gb + s) * GATES + q * HID + j]);
    }

    float bias[4], wihr[4][DIN];
    if (PHASE == 1 && kh < 2) {
#pragma unroll
        for (int q = 0; q < 4; q++) {
            int r = q * HID + j;
            bias[q] = __ldg(bih + r) + __ldg(bhh + r);
#pragma unroll
            for (int d = 0; d < DIN; d++) wihr[q][d] = __ldg(wih0 + r * DIN + d);
        }
    }

    {
        const float4* src = (const float4*)Pg;
        float4*       dst = (float4*)(sm + OFF_WC);
        for (int i = tid; i < NSM * GATES; i += NTH) dst[i] = __ldg(src + i);
    }
    for (int i = tid; i < 1024; i += NTH) sm[OFF_HA + i] = 0.f;
    __syncthreads();

    const ulonglong2* WcD = (const ulonglong2*)(sm + OFF_WC);

    float c[2][2] = {{0.f, 0.f}, {0.f, 0.f}};
    float2 xqA[4], xqB[4];
    float  xvA[2][DIN], xvB[2][DIN];

    // -------- export helpers --------
    auto exportA = [&](float (&pr)[4][4], float (&prOwn)[4][2]) {
        float* XP = sm + OFF_XP;               // half A
        if (kh == 0) {
#pragma unroll
            for (int r = 2; r < 4; r++)
                *(float4*)(XP + r * 512 + j * 4) =
                    make_float4(pr[0][r], pr[1][r], pr[2][r], pr[3][r]);
#pragma unroll
            for (int q = 0; q < 4; q++) { prOwn[q][0] = pr[q][0]; prOwn[q][1] = pr[q][1]; }
        } else if (kh == 1) {
#pragma unroll
            for (int r = 0; r < 2; r++)
                *(float4*)(XP + r * 512 + j * 4) =
                    make_float4(pr[0][r], pr[1][r], pr[2][r], pr[3][r]);
#pragma unroll
            for (int q = 0; q < 4; q++) { prOwn[q][0] = pr[q][2]; prOwn[q][1] = pr[q][3]; }
        } else {
#pragma unroll
            for (int r = 0; r < 4; r++)
                *(float4*)(XP + 2048 + r * 512 + j * 4) =
                    make_float4(pr[0][r], pr[1][r], pr[2][r], pr[3][r]);
        }
    };
    auto exportB = [&](float (&pr)[4][3], float (&prOwn)[4][3]) {
        float* XP = sm + OFF_XP + 4096;        // half B
        if (kh == 0) {
            *(float4*)(XP + 2 * 512 + j * 4) =
                make_float4(pr[0][2], pr[1][2], pr[2][2], pr[3][2]);
#pragma unroll
            for (int q = 0; q < 4; q++) { prOwn[q][0] = pr[q][0]; prOwn[q][1] = pr[q][1]; }
        } else if (kh == 1) {
#pragma unroll
            for (int r = 0; r < 2; r++)
                *(float4*)(XP + r * 512 + j * 4) =
                    make_float4(pr[0][r], pr[1][r], pr[2][r], pr[3][r]);
#pragma unroll
            for (int q = 0; q < 4; q++) prOwn[q][0] = pr[q][2];
        } else {
#pragma unroll
            for (int r = 0; r < 3; r++)
                *(float4*)(XP + 2048 + r * 512 + j * 4) =
                    make_float4(pr[0][r], pr[1][r], pr[2][r], pr[3][r]);
        }
    };

    auto finalize_half = [&](int hoff, int half, int t, const float* prOwn0, const float* prOwn1,
                             float2 (&xq)[4], float (&xv)[2][DIN]) {
        const float* XP = sm + OFF_XP + half * 4096;
        const int nown = (kh == 0) ? 2 : (half == 0 ? 2 : 1);
#pragma unroll
        for (int r2 = 0; r2 < 2; r2++) {
            if (r2 >= nown) break;
            int rloc = 2 * kh + r2;
            const float* po = (r2 == 0) ? prOwn0 : prOwn1;
            float4 p0 = *(const float4*)(XP + rloc * 512 + j * 4);
            float4 p1 = *(const float4*)(XP + 2048 + rloc * 512 + j * 4);
            float gate[4];
            gate[0] = po[0] + p0.x + p1.x;
            gate[1] = po[1] + p0.y + p1.y;
            gate[2] = po[2] + p0.z + p1.z;
            gate[3] = po[3] + p0.w + p1.w;
            if (PHASE == 1) {
#pragma unroll
                for (int q = 0; q < 4; q++) {
                    float s = bias[q];
#pragma unroll
                    for (int d = 0; d < DIN; d++) s = fmaf(wihr[q][d], xv[r2][d], s);
                    gate[q] += s;
                }
            } else {
                gate[0] += (r2 == 0 ? xq[0].x : xq[0].y);
                gate[1] += (r2 == 0 ? xq[1].x : xq[1].y);
                gate[2] += (r2 == 0 ? xq[2].x : xq[2].y);
                gate[3] += (r2 == 0 ? xq[3].x : xq[3].y);
            }
            float cc = sigf(gate[1]) * c[half][r2] + sigf(gate[0]) * tanhf_fast(gate[2]);
            c[half][r2] = cc;
            float h = sigf(gate[3]) * tanhf_fast(cc);
            sm[hoff + rloc * HID + j] = h;
            if (PHASE == 1)
                g_h1[((size_t)(blk * S_LEN + t) * BST + half * 4 + rloc) * HID + j] =
                    __uint_as_float(f2tf32(h));   // pre-round for tensor-core gemm
        }
    };

    auto load_inputs = [&](int half, int t, float2 (&xq)[4], float (&xv)[2][DIN]) {
        if (kh >= 2) return;
        if (PHASE == 2) {
            const float* xp = g_xg1 + (size_t)(blk * S_LEN + t) * (GATES * BST);
            int off = half * 4 + 2 * kh;
#pragma unroll
            for (int q = 0; q < 4; q++)
                xq[q] = __ldg((const float2*)(xp + (q * HID + j) * BST + off));
        } else {
#pragma unroll
            for (int r2 = 0; r2 < 2; r2++) {
                int gr = bg0 + half * 4 + 2 * kh + r2;
                if (gr > BATCH - 1) gr = BATCH - 1;
                const float* xr = x + ((size_t)gr * S_LEN + t) * DIN;
#pragma unroll
                for (int d = 0; d < DIN; d++) xv[r2][d] = __ldg(xr + d);
            }
        }
    };

    float prOwnA[4][2];
    float prOwnBv[4][3];

    for (int t = 0; t < S_LEN; t++) {
        // ---- alpha: GEMM_A(t) + finalize_B(t-1) ----
        load_inputs(0, t, xqA, xvA);
        if (t > 0 && kh < 2) {
            float o0[4] = {prOwnBv[0][0], prOwnBv[1][0], prOwnBv[2][0], prOwnBv[3][0]};
            float o1[4] = {prOwnBv[0][1], prOwnBv[1][1], prOwnBv[2][1], prOwnBv[3][1]};
            finalize_half(OFF_HB, 1, t - 1, o0, o1, xqB, xvB);
        }
        {
            float prA[4][4];
            gemm_body<4>(kh, WcD, wr, gb, (const ulonglong2*)(sm + OFF_HA), j, prA);
            exportA(prA, prOwnA);
            __syncthreads();
            // ---- beta: GEMM_B(t) + finalize_A(t) ----
            load_inputs(1, t, xqB, xvB);
            if (kh < 2) {
                float o0[4] = {prOwnA[0][0], prOwnA[1][0], prOwnA[2][0], prOwnA[3][0]};
                float o1[4] = {prOwnA[0][1], prOwnA[1][1], prOwnA[2][1], prOwnA[3][1]};
                finalize_half(OFF_HA, 0, t, o0, o1, xqA, xvA);
            }
        }
        {
            float prBt[4][3];
            gemm_body<3>(kh, WcD, wr, gb, (const ulonglong2*)(sm + OFF_HB), j, prBt);
            exportB(prBt, prOwnBv);
        }
        __syncthreads();
    }
    // drain: finalize_B(511)
    if (kh < 2) {
        float o0[4] = {prOwnBv[0][0], prOwnBv[1][0], prOwnBv[2][0], prOwnBv[3][0]};
        float o1[4] = {prOwnBv[0][1], prOwnBv[1][1], prOwnBv[2][1], prOwnBv[3][1]};
        finalize_half(OFF_HB, 1, S_LEN - 1, o0, o1, xqB, xvB);
    }
    __syncthreads();

    if (PHASE == 2 && tid < 224) {
        int w = tid >> 5, lane = tid & 31;
        if (w < valid) {
            const float* hrow = sm + (w < 4 ? OFF_HA + w * HID : OFF_HB + (w - 4) * HID);
            float s = 0.f;
#pragma unroll
            for (int m = 0; m < HID; m += 32)
                s += hrow[lane + m] * __ldg(fcw + lane + m);
#pragma unroll
            for (int o = 16; o > 0; o >>= 1) s += __shfl_down_sync(0xffffffffu, s, o);
            if (lane == 0) out[bg0 + w] = s + __ldg(fcb);
        }
    }
}

// ---------------- launch ----------------
extern "C" void kernel_launch(void* const* d_in, const int* in_sizes, int n_in,
                              void* d_out, int out_size) {
    const float* x    = (const float*)d_in[0];
    const float* wih0 = (const float*)d_in[1];
    const float* whh0 = (const float*)d_in[2];
    const float* bih0 = (const float*)d_in[3];
    const float* bhh0 = (const float*)d_in[4];
    const float* wih1 = (const float*)d_in[5];
    const float* whh1 = (const float*)d_in[6];
    const float* bih1 = (const float*)d_in[7];
    const float* bhh1 = (const float*)d_in[8];
    const float* fcw  = (const float*)d_in[9];
    const float* fcb  = (const float*)d_in[10];
    float* out = (float*)d_out;
    (void)in_sizes; (void)n_in; (void)out_size;

    cudaFuncSetAttribute(lstm_phase<1>, cudaFuncAttributeMaxDynamicSharedMemorySize, PH_SMEM_BYTES);
    cudaFuncSetAttribute(lstm_phase<2>, cudaFuncAttributeMaxDynamicSharedMemorySize, PH_SMEM_BYTES);
    cudaFuncSetAttribute(xg1_mma,       cudaFuncAttributeMaxDynamicSharedMemorySize, TG_SMEM_BYTES);

    pack_kernel<<<(GATES * HID + 255) / 256, 256>>>(whh0, whh1);
    lstm_phase<1><<<NBLK, NTH, PH_SMEM_BYTES>>>(x, wih0, bih0, bhh0, fcw, fcb, out);
    xg1_mma<<<dim3(64, NBLK), TG_THREADS, TG_SMEM_BYTES>>>(wih1, bih1, bhh1);
    lstm_phase<2><<<NBLK, NTH, PH_SMEM_BYTES>>>(x, wih0, bih1, bhh1, fcw, fcb, out);
}

// round 17
// speedup vs baseline: 2.4607x; 1.7322x over previous
#include <cuda_runtime.h>

// ---------------- problem constants ----------------
#define S_LEN  512
#define DIN    5
#define HID    128
#define GATES  512
#define BATCH  1024
#define NBLK   147     // recurrence blocks: 146 x 7 rows + 1 x 2 rows
#define RPB    7
#define BST    8       // row stride in g_h1 / g_xg1 (padded)

// phase-mma config
#define PTH 512        // phase threads = 16 warps x 32 gate-cols
#define HP  132        // h tile pitch (conflict-free A frags)
#define GP  520        // gate buffer pitch (conflict-free C stores)
#define PH_SMEM(KREG) ((((16-(KREG))*4096) + 8*HP + 8*GP) * 4)

// xg1 gemm smem (unchanged from R16): A[64][132] + B[64][132] + C[4096]
#define TG_THREADS 256
#define TG_PAD 132
#define TG_A_FLOATS (64*TG_PAD)
#define TG_B_FLOATS (64*TG_PAD)
#define TG_C_OFF    (TG_A_FLOATS + TG_B_FLOATS)
#define TG_SMEM_BYTES ((TG_C_OFF + 4096)*4)   // 83968 -> 2 CTAs/SM

// ---------------- global scratch (static) ----------------
// fragment-ordered tf32 weights: [ks(16)][col(512)][2*tig+d]  (d=0: k=8ks+tig, d=1: +4)
__device__ __align__(16) unsigned g_PF1[16 * GATES * 8];   // w_hh0
__device__ __align__(16) unsigned g_PF2[16 * GATES * 8];   // w_hh1
__device__ __align__(16) float g_h1 [(size_t)NBLK * S_LEN * BST * HID];    // tf32-rounded
__device__ __align__(16) float g_xg1[(size_t)NBLK * S_LEN * GATES * BST];

// ---------------- helpers ----------------
typedef unsigned long long u64;
__device__ __forceinline__ unsigned f2tf32(float f) {
    unsigned r;
    asm("cvt.rna.tf32.f32 %0, %1;" : "=r"(r) : "f"(f));
    return r;
}
__device__ __forceinline__ void mma_tf32(float (&d)[4], const unsigned (&a)[4],
                                         const unsigned (&b)[2]) {
    asm("mma.sync.aligned.m16n8k8.row.col.f32.tf32.tf32.f32 "
        "{%0,%1,%2,%3}, {%4,%5,%6,%7}, {%8,%9}, {%0,%1,%2,%3};"
        : "+f"(d[0]), "+f"(d[1]), "+f"(d[2]), "+f"(d[3])
        : "r"(a[0]), "r"(a[1]), "r"(a[2]), "r"(a[3]), "r"(b[0]), "r"(b[1]));
}
__device__ __forceinline__ float tanh_a(float x) {
    float r;
    asm("tanh.approx.f32 %0, %1;" : "=f"(r) : "f"(x));
    return r;
}
__device__ __forceinline__ float sig_a(float x) {
    return fmaf(tanh_a(0.5f * x), 0.5f, 0.5f);
}

// ---------------- K1: pack weights into tf32 mma-fragment order ----------------
__global__ void pack_kernel(const float* __restrict__ whh0,
                            const float* __restrict__ whh1) {
    int i = blockIdx.x * blockDim.x + threadIdx.x;
    if (i >= GATES * HID) return;
    int col = i >> 7, k = i & 127;
    int ks = k >> 3, kin = k & 7, tig = kin & 3, d = kin >> 2;
    int idx = (ks * GATES + col) * 8 + 2 * tig + d;
    g_PF1[idx] = f2tf32(whh0[col * HID + k]);
    g_PF2[idx] = f2tf32(whh1[col * HID + k]);
}

// ---------------- K3: xg1 = h1 @ w_ih1^T + biases (tf32 mma, unchanged R16) ----------------
__global__ void __launch_bounds__(TG_THREADS, 2) xg1_mma(
    const float* __restrict__ wih1,
    const float* __restrict__ bih1,
    const float* __restrict__ bhh1)
{
    extern __shared__ float smf[];
    unsigned* As = (unsigned*)smf;
    unsigned* Bs = (unsigned*)(smf + TG_A_FLOATS);
    float*    Cs = smf + TG_C_OFF;

    const int tid  = threadIdx.x;
    const int lane = tid & 31;
    const int wid  = tid >> 5;
    const int wm   = wid >> 1;
    const int wn   = wid & 1;
    const int mt   = blockIdx.x;
    const int blk  = blockIdx.y;
    const int t0   = mt * 8;

    float4 bpre[8];
    auto loadB = [&](int nt) {
        const float4* Bg = (const float4*)(wih1 + (size_t)nt * 64 * HID);
#pragma unroll
        for (int k = 0; k < 8; k++) bpre[k] = __ldg(Bg + tid + 256 * k);
    };
    auto stsB = [&]() {
#pragma unroll
        for (int k = 0; k < 8; k++) {
            int i = tid + 256 * k;
            int row = i >> 5, c4 = i & 31;
            unsigned* bd = Bs + row * TG_PAD + c4 * 4;
            bd[0] = f2tf32(bpre[k].x); bd[1] = f2tf32(bpre[k].y);
            bd[2] = f2tf32(bpre[k].z); bd[3] = f2tf32(bpre[k].w);
        }
    };

    loadB(0);
    {
        const float4* Ag = (const float4*)(g_h1 + (size_t)(blk * S_LEN + t0) * (BST * HID));
#pragma unroll
        for (int k = 0; k < 8; k++) {
            int i = tid + 256 * k;
            int row = i >> 5, c4 = i & 31;
            float4 av = __ldg(Ag + i);
            *(float4*)((float*)As + row * TG_PAD + c4 * 4) = av;
        }
    }
    stsB();
    __syncthreads();

    const int g   = lane >> 2;
    const int tig = lane & 3;

    for (int nt = 0; nt < 8; nt++) {
        const int n0 = nt * 64;
        if (nt + 1 < 8) loadB(nt + 1);

        float acc[4][4];
#pragma unroll
        for (int ns = 0; ns < 4; ns++)
#pragma unroll
            for (int e = 0; e < 4; e++) acc[ns][e] = 0.f;

#pragma unroll 2
        for (int ks = 0; ks < 16; ks++) {
            const int k0 = ks * 8;
            unsigned a[4], b[4][2];
            int r0 = wm * 16 + g;
            a[0] = As[r0 * TG_PAD + k0 + tig];
            a[1] = As[(r0 + 8) * TG_PAD + k0 + tig];
            a[2] = As[r0 * TG_PAD + k0 + tig + 4];
            a[3] = As[(r0 + 8) * TG_PAD + k0 + tig + 4];
#pragma unroll
            for (int ns = 0; ns < 4; ns++) {
                int nb = wn * 32 + ns * 8 + g;
                b[ns][0] = Bs[nb * TG_PAD + k0 + tig];
                b[ns][1] = Bs[nb * TG_PAD + k0 + tig + 4];
            }
#pragma unroll
            for (int ns = 0; ns < 4; ns++)
                mma_tf32(acc[ns], a, b[ns]);
        }
        __syncthreads();

#pragma unroll
        for (int ns = 0; ns < 4; ns++) {
            int r0 = wm * 16 + g;
            int r2 = r0 + 8;
            int c0 = wn * 32 + ns * 8 + 2 * tig;
            Cs[(r0 >> 3) * 512 + c0 * 8 + (r0 & 7)]       = acc[ns][0];
            Cs[(r0 >> 3) * 512 + (c0 + 1) * 8 + (r0 & 7)] = acc[ns][1];
            Cs[(r2 >> 3) * 512 + c0 * 8 + (r2 & 7)]       = acc[ns][2];
            Cs[(r2 >> 3) * 512 + (c0 + 1) * 8 + (r2 & 7)] = acc[ns][3];
        }
        if (nt + 1 < 8) stsB();
        __syncthreads();

        for (int i = tid; i < 1024; i += TG_THREADS) {
            int tloc = i >> 7;
            int rest = i & 127;
            int n = rest >> 1;
            float4 v = ((const float4*)Cs)[i];
            float bias = __ldg(bih1 + n0 + n) + __ldg(bhh1 + n0 + n);
            v.x += bias; v.y += bias; v.z += bias; v.w += bias;
            ((float4*)(g_xg1 + ((size_t)((blk * S_LEN + t0 + tloc) * GATES) + n0) * BST))[rest] = v;
        }
    }
}

// ---------------- K2/K4: tensor-core recurrent phases ----------------
// 512 thr = 16 warps; warp w owns gate cols [32w, 32w+32) = 4 n-tiles, full K=128.
// Per step: one m16n8k8 pass (A = h[rows 0-6, rows 8-15 zero]) -> gate buffer ->
// barrier -> distributed finalize (2 (j,b) pairs/thread) -> barrier.
// Weights: ks < KREG register-resident fragments; ks >= KREG from smem.
template<int PHASE, int KREG>
__global__ void __launch_bounds__(PTH, 1) lstm_phase_mma(
    const float* __restrict__ x,
    const float* __restrict__ wih0,
    const float* __restrict__ bih,
    const float* __restrict__ bhh,
    const float* __restrict__ fcw,
    const float* __restrict__ fcb,
    float* __restrict__ out)
{
    extern __shared__ float sm[];
    float* Hs = sm + (16 - KREG) * 4096;   // h tile [8 rows][HP]
    float* Gb = Hs + 8 * HP;               // gate buffer [8 b][GP]
    const unsigned* PF = (PHASE == 1) ? g_PF1 : g_PF2;

    const int tid  = threadIdx.x;
    const int lane = tid & 31;
    const int wid  = tid >> 5;             // 0..15
    const int g    = lane >> 2;            // 0..7
    const int tig  = lane & 3;             // 0..3
    const int cb   = wid * 32;             // warp gate-col base
    const int blk  = blockIdx.x;
    const int bg0  = blk * RPB;
    const int valid = (BATCH - bg0 < RPB) ? (BATCH - bg0) : RPB;

    // finalize mapping: pair0 b=fb0 (0..3), pair1 b=fb1=fb0+4 (4..7; valid if <7)
    const int fj  = tid & 127;
    const int fb0 = tid >> 7;
    const int fb1 = fb0 + 4;

    // register-resident B fragments (ks < KREG)
    u64 breg[4][KREG];
#pragma unroll
    for (int nt = 0; nt < 4; nt++)
#pragma unroll
        for (int ks = 0; ks < KREG; ks++)
            breg[nt][ks] = *(const u64*)(PF + (size_t)(ks * GATES + cb + nt * 8 + g) * 8 + 2 * tig);

    // phase1 finalize constants
    float biasq[4], wihr[4][DIN];
    if (PHASE == 1) {
#pragma unroll
        for (int q = 0; q < 4; q++) {
            int r = q * HID + fj;
            biasq[q] = __ldg(bih + r) + __ldg(bhh + r);
#pragma unroll
            for (int d = 0; d < DIN; d++) wihr[q][d] = __ldg(wih0 + r * DIN + d);
        }
    }

    // smem weights (ks KREG..15), zero h tile
    {
        const float4* src = (const float4*)(PF + (size_t)KREG * 4096);
        float4*       dst = (float4*)sm;
        for (int i = tid; i < (16 - KREG) * 1024; i += PTH) dst[i] = __ldg(src + i);
    }
    for (int i = tid; i < 8 * HP; i += PTH) Hs[i] = 0.f;
    __syncthreads();

    float c0 = 0.f, c1 = 0.f;

    for (int t = 0; t < S_LEN; t++) {
        // early finalize-input loads
        float xq0[4], xq1[4], xv0[DIN], xv1[DIN];
        if (PHASE == 2) {
            const float* xp = g_xg1 + (size_t)(blk * S_LEN + t) * (GATES * BST);
#pragma unroll
            for (int q = 0; q < 4; q++) {
                xq0[q] = __ldg(xp + (q * HID + fj) * BST + fb0);
                xq1[q] = __ldg(xp + (q * HID + fj) * BST + fb1);
            }
        } else {
            int r0 = bg0 + fb0; if (r0 > BATCH - 1) r0 = BATCH - 1;
            int r1 = bg0 + fb1; if (r1 > BATCH - 1) r1 = BATCH - 1;
#pragma unroll
            for (int d = 0; d < DIN; d++) {
                xv0[d] = __ldg(x + ((size_t)r0 * S_LEN + t) * DIN + d);
                xv1[d] = __ldg(x + ((size_t)r1 * S_LEN + t) * DIN + d);
            }
        }

        // ---- mma: gates = h @ W^T ----
        float acc[4][4];
#pragma unroll
        for (int nt = 0; nt < 4; nt++)
#pragma unroll
            for (int e = 0; e < 4; e++) acc[nt][e] = 0.f;

#pragma unroll
        for (int ks = 0; ks < 16; ks++) {
            const int k0 = ks * 8;
            unsigned av[4];
            av[0] = __float_as_uint(Hs[g * HP + k0 + tig]);
            av[2] = __float_as_uint(Hs[g * HP + k0 + tig + 4]);
            av[1] = 0u; av[3] = 0u;      // rows 8-15 are zero
#pragma unroll
            for (int nt = 0; nt < 4; nt++) {
                u64 bv;
                if (ks < KREG) bv = breg[nt][ks];
                else bv = *(const u64*)(sm + (size_t)(ks - KREG) * 4096
                                          + (cb + nt * 8 + g) * 8 + 2 * tig);
                unsigned bb[2] = {(unsigned)(bv & 0xffffffffu), (unsigned)(bv >> 32)};
                mma_tf32(acc[nt], av, bb);
            }
        }

        // C -> gate buffer (row g valid for g<7; rows g+8 discarded)
        if (g < RPB) {
#pragma unroll
            for (int nt = 0; nt < 4; nt++)
                *(float2*)(Gb + g * GP + cb + nt * 8 + 2 * tig) =
                    make_float2(acc[nt][0], acc[nt][1]);
        }
        __syncthreads();   // 1: C visible; all h reads done

        // ---- finalize: 2 (j,b) pairs per thread ----
        {
            float gate[4];
#pragma unroll
            for (int q = 0; q < 4; q++) gate[q] = Gb[fb0 * GP + q * HID + fj];
            if (PHASE == 1) {
#pragma unroll
                for (int q = 0; q < 4; q++) {
                    float s = biasq[q];
#pragma unroll
                    for (int d = 0; d < DIN; d++) s = fmaf(wihr[q][d], xv0[d], s);
                    gate[q] += s;
                }
            } else {
#pragma unroll
                for (int q = 0; q < 4; q++) gate[q] += xq0[q];
            }
            float cc = sig_a(gate[1]) * c0 + sig_a(gate[0]) * tanh_a(gate[2]);
            c0 = cc;
            float h = sig_a(gate[3]) * tanh_a(cc);
            float hr = __uint_as_float(f2tf32(h));
            Hs[fb0 * HP + fj] = hr;
            if (PHASE == 1)
                g_h1[((size_t)(blk * S_LEN + t) * BST + fb0) * HID + fj] = hr;
        }
        if (fb1 < RPB) {
            float gate[4];
#pragma unroll
            for (int q = 0; q < 4; q++) gate[q] = Gb[fb1 * GP + q * HID + fj];
            if (PHASE == 1) {
#pragma unroll
                for (int q = 0; q < 4; q++) {
                    float s = biasq[q];
#pragma unroll
                    for (int d = 0; d < DIN; d++) s = fmaf(wihr[q][d], xv1[d], s);
                    gate[q] += s;
                }
            } else {
#pragma unroll
                for (int q = 0; q < 4; q++) gate[q] += xq1[q];
            }
            float cc = sig_a(gate[1]) * c1 + sig_a(gate[0]) * tanh_a(gate[2]);
            c1 = cc;
            float h = sig_a(gate[3]) * tanh_a(cc);
            float hr = __uint_as_float(f2tf32(h));
            Hs[fb1 * HP + fj] = hr;
            if (PHASE == 1)
                g_h1[((size_t)(blk * S_LEN + t) * BST + fb1) * HID + fj] = hr;
        }
        __syncthreads();   // 2: h(t+1) visible before next mma
    }

    // FC epilogue (phase 2)
    if (PHASE == 2 && tid < 224) {
        int w = tid >> 5, ln = tid & 31;
        if (w < valid) {
            const float* hrow = Hs + w * HP;
            float s = 0.f;
#pragma unroll
            for (int m = 0; m < HID; m += 32)
                s += hrow[ln + m] * __ldg(fcw + ln + m);
#pragma unroll
            for (int o = 16; o > 0; o >>= 1) s += __shfl_down_sync(0xffffffffu, s, o);
            if (ln == 0) out[bg0 + w] = s + __ldg(fcb);
        }
    }
}

// ---------------- launch ----------------
extern "C" void kernel_launch(void* const* d_in, const int* in_sizes, int n_in,
                              void* d_out, int out_size) {
    const float* x    = (const float*)d_in[0];
    const float* wih0 = (const float*)d_in[1];
    const float* whh0 = (const float*)d_in[2];
    const float* bih0 = (const float*)d_in[3];
    const float* bhh0 = (const float*)d_in[4];
    const float* wih1 = (const float*)d_in[5];
    const float* whh1 = (const float*)d_in[6];
    const float* bih1 = (const float*)d_in[7];
    const float* bhh1 = (const float*)d_in[8];
    const float* fcw  = (const float*)d_in[9];
    const float* fcb  = (const float*)d_in[10];
    float* out = (float*)d_out;
    (void)in_sizes; (void)n_in; (void)out_size;

    cudaFuncSetAttribute((const void*)lstm_phase_mma<1, 4>,
                         cudaFuncAttributeMaxDynamicSharedMemorySize, PH_SMEM(4));
    cudaFuncSetAttribute((const void*)lstm_phase_mma<2, 8>,
                         cudaFuncAttributeMaxDynamicSharedMemorySize, PH_SMEM(8));
    cudaFuncSetAttribute((const void*)xg1_mma,
                         cudaFuncAttributeMaxDynamicSharedMemorySize, TG_SMEM_BYTES);

    pack_kernel<<<(GATES * HID + 255) / 256, 256>>>(whh0, whh1);
    lstm_phase_mma<1, 4><<<NBLK, PTH, PH_SMEM(4)>>>(x, wih0, bih0, bhh0, fcw, fcb, out);
    xg1_mma<<<dim3(64, NBLK), TG_THREADS, TG_SMEM_BYTES>>>(wih1, bih1, bhh1);
    lstm_phase_mma<2, 8><<<NBLK, PTH, PH_SMEM(8)>>>(x, wih0, bih1, bhh1, fcw, fcb, out);
}